// round 11
// baseline (speedup 1.0000x reference)
#include <cuda_runtime.h>
#include <cuda_fp16.h>
#include <cstdint>
#include <math.h>

#define PWH 72
#define NTH 512

struct SmC {
    __half tile[8][66][PWH];   // fp16 padded tile; interior rows 1..64, cols 2..65
    float rowsum[8][64];
    float colm[8][64];
    float sh[8][64];
    float sw[8][64];
    float wt[4096];
    float w1s[64];
    float w3s[576];
    float b1s[8], b3s[8], gnws[8], gnbs[8];
    float S2l[8];
    float Sgp[8][2], Sg2p[8][2];
    float Aarr[8], Kpart[8];
    float Weff[72];
};

// sigmoid via single-MUFU tanh.approx: sigmoid(x) = 0.5*tanh(0.5x) + 0.5
__device__ __forceinline__ float sigf(float v) {
    float t;
    asm("tanh.approx.f32 %0, %1;" : "=f"(t) : "f"(v * 0.5f));
    return fmaf(t, 0.5f, 0.5f);
}

// load 12 consecutive padded halfs (16B-aligned) -> 12 floats
__device__ __forceinline__ void ld12(const __half* p, float* w) {
    uint4 a = *(const uint4*)p;
    uint2 b = *(const uint2*)(p + 8);
    float2 f;
    f = __half22float2(*(__half2*)&a.x); w[0] = f.x;  w[1] = f.y;
    f = __half22float2(*(__half2*)&a.y); w[2] = f.x;  w[3] = f.y;
    f = __half22float2(*(__half2*)&a.z); w[4] = f.x;  w[5] = f.y;
    f = __half22float2(*(__half2*)&a.w); w[6] = f.x;  w[7] = f.y;
    f = __half22float2(*(__half2*)&b.x); w[8] = f.x;  w[9] = f.y;
    f = __half22float2(*(__half2*)&b.y); w[10] = f.x; w[11] = f.y;
}

__global__ void __launch_bounds__(NTH, 2)
fused_kernel(const float* __restrict__ x,
             const float* __restrict__ w1, const float* __restrict__ b1,
             const float* __restrict__ w3, const float* __restrict__ b3,
             const float* __restrict__ gnw, const float* __restrict__ gnb,
             float* __restrict__ out)
{
    extern __shared__ char smraw[];
    SmC& s = *reinterpret_cast<SmC*>(smraw);
    const int tid = threadIdx.x;
    const long long g = blockIdx.x;
    const float* src = x + g * 32768;
    float* dst = out + g * 32768;
    const float4* src4 = reinterpret_cast<const float4*>(src);

    // ---- phase A: border zeros + params + interior load (fp16 STS) ----
    {
        const __half hz = __float2half(0.f);
        for (int t = tid; t < 8 * 656; t += NTH) {
            int c = t / 656;
            int u = t % 656;
            if (u < 144) {
                int row = (u < 72) ? 0 : 65;
                int col = (u < 72) ? u : (u - 72);
                s.tile[c][row][col] = hz;
            } else {
                int u2 = u - 144;            // 0..511
                int row = (u2 >> 3) + 1;     // 1..64
                int m = u2 & 7;
                int col = (m < 2) ? m : (64 + m);
                s.tile[c][row][col] = hz;
            }
        }
    }
    if (tid < 64) s.w1s[tid] = w1[tid];
    if (tid >= 64 && tid < 72) {
        int c = tid - 64;
        s.b1s[c] = b1[c]; s.b3s[c] = b3[c];
        s.gnws[c] = gnw[c]; s.gnbs[c] = gnb[c];
    }
    for (int t = tid; t < 576; t += NTH) s.w3s[t] = w3[t];

    #pragma unroll
    for (int k = 0; k < 16; k++) {
        int l4 = tid + NTH * k;
        int c = l4 >> 10;
        int i = (l4 >> 4) & 63;
        int j4 = (l4 & 15) << 2;
        float4 v = src4[c * 1024 + i * 16 + (j4 >> 2)];
        __half2* p = (__half2*)&s.tile[c][i + 1][j4 + 2];
        p[0] = __floats2half2_rn(v.x, v.y);
        p[1] = __floats2half2_rn(v.z, v.w);
    }
    __syncthreads();

    // ---- phase B: rowsums (512 units) + colsums (256 half2-pair units) ----
    {
        int c = tid >> 6, i = tid & 63;
        const uint4* rp = reinterpret_cast<const uint4*>(&s.tile[c][i + 1][0]);
        __half2 a0 = __float2half2_rn(0.f), a1 = a0, a2 = a0, a3 = a0;
        #pragma unroll
        for (int q = 0; q < 9; q++) {
            uint4 u = rp[q];
            a0 = __hadd2(a0, *(__half2*)&u.x);
            a1 = __hadd2(a1, *(__half2*)&u.y);
            a2 = __hadd2(a2, *(__half2*)&u.z);
            a3 = __hadd2(a3, *(__half2*)&u.w);
        }
        __half2 hs = __hadd2(__hadd2(a0, a1), __hadd2(a2, a3));
        float2 f = __half22float2(hs);
        s.rowsum[c][i] = f.x + f.y;
    }
    if (tid < 256) {
        int c = tid >> 5, jp = tid & 31;     // columns 2jp, 2jp+1
        const __half2* cp = (const __half2*)&s.tile[c][1][2 + 2 * jp];
        __half2 a0 = __float2half2_rn(0.f), a1 = a0, a2 = a0, a3 = a0;
        #pragma unroll
        for (int r = 0; r < 64; r += 4) {
            a0 = __hadd2(a0, cp[r * (PWH / 2)]);
            a1 = __hadd2(a1, cp[(r + 1) * (PWH / 2)]);
            a2 = __hadd2(a2, cp[(r + 2) * (PWH / 2)]);
            a3 = __hadd2(a3, cp[(r + 3) * (PWH / 2)]);
        }
        float2 f = __half22float2(__hadd2(__hadd2(a0, a1), __hadd2(a2, a3)));
        *(float2*)&s.colm[c][2 * jp] = f;
    }
    __syncthreads();

    // ---- phase C: sh + sw (512 units each) + warp0: T (shfl) + S2l ----
    {
        const float inv = 1.0f / 64.0f;
        int o = tid >> 6, i = tid & 63;
        float acc = s.b1s[o], acc2 = s.b1s[o];
        #pragma unroll
        for (int c = 0; c < 8; c++) {
            float wv = s.w1s[o * 8 + c];
            acc  += wv * (s.rowsum[c][i] * inv);
            acc2 += wv * (s.colm[c][i] * inv);
        }
        s.sh[o][i] = sigf(acc);
        s.sw[o][i] = sigf(acc2);
    }
    if (tid < 32) {
        int lane = tid;
        int c = lane & 7;
        float Tc = 0.f;
        if (lane < 8) {
            float a0 = 0.f, a1 = 0.f, a2 = 0.f, a3 = 0.f;
            #pragma unroll
            for (int j = 0; j < 64; j += 4) {
                a0 += s.colm[c][j];     a1 += s.colm[c][j + 1];
                a2 += s.colm[c][j + 2]; a3 += s.colm[c][j + 3];
            }
            Tc = (a0 + a1) + (a2 + a3);
        }
        float acc = 0.f;
        #pragma unroll
        for (int ci = 0; ci < 8; ci++) {
            float T   = __shfl_sync(0xffffffffu, Tc, ci);
            float r0  = s.rowsum[ci][0], r63 = s.rowsum[ci][63];
            float c0  = s.colm[ci][0],   c63 = s.colm[ci][63];
            float g00 = __half2float(s.tile[ci][1][2]);
            float g0e = __half2float(s.tile[ci][1][65]);
            float ge0 = __half2float(s.tile[ci][64][2]);
            float gee = __half2float(s.tile[ci][64][65]);
            float Sv[9];
            Sv[0] = T - r63 - c63 + gee;
            Sv[1] = T - r63;
            Sv[2] = T - r63 - c0 + ge0;
            Sv[3] = T - c63;
            Sv[4] = T;
            Sv[5] = T - c0;
            Sv[6] = T - r0 - c63 + g0e;
            Sv[7] = T - r0;
            Sv[8] = T - r0 - c0 + g00;
            const float* wp = &s.w3s[c * 72 + ci * 9];
            #pragma unroll
            for (int t = 0; t < 9; t++) acc += wp[t] * Sv[t];
        }
        if (lane < 8)
            s.S2l[c] = acc * (1.0f / 4096.0f) + s.b3s[c];
    }
    __syncthreads();

    // ---- phase D: gated stats (16 warps: channel x row-half) ----
    {
        int w = tid >> 5;
        int c = w >> 1;
        int half = w & 1;
        int lane = tid & 31;
        float2 swp = *(const float2*)&s.sw[c][2 * lane];
        float s0 = 0.f, s1 = 0.f, q0 = 0.f, q1 = 0.f;
        int ibase = half * 32;
        #pragma unroll 4
        for (int r = 0; r < 32; r++) {
            int i = ibase + r;
            float shi = s.sh[c][i];
            __half2 h = *(const __half2*)&s.tile[c][i + 1][2 + 2 * lane];
            float2 gf = __half22float2(h);
            float v0 = gf.x * (shi * swp.x);
            float v1 = gf.y * (shi * swp.y);
            s0 += v0; s1 += v1;
            q0 += v0 * v0; q1 += v1 * v1;
        }
        float sum = s0 + s1, sq = q0 + q1;
        #pragma unroll
        for (int off = 16; off; off >>= 1) {
            sum += __shfl_xor_sync(0xffffffffu, sum, off);
            sq  += __shfl_xor_sync(0xffffffffu, sq,  off);
        }
        if (lane == 0) { s.Sgp[c][half] = sum; s.Sg2p[c][half] = sq; }
    }
    __syncthreads();

    // ---- phase E: redundant softmaxes (80 threads) -> Weff / Aarr / Kpart ----
    if (tid < 80) {
        float mx1 = -1e30f, mx2 = -1e30f;
        #pragma unroll
        for (int k = 0; k < 8; k++) {
            mx1 = fmaxf(mx1, s.gnbs[k]);
            mx2 = fmaxf(mx2, s.S2l[k]);
        }
        float e1[8], e2[8];
        float d1 = 0.f, d2 = 0.f;
        #pragma unroll
        for (int k = 0; k < 8; k++) {
            e1[k] = __expf(s.gnbs[k] - mx1); d1 += e1[k];
            e2[k] = __expf(s.S2l[k] - mx2);  d2 += e2[k];
        }
        if (tid < 72) {
            int ci = tid / 9, tap = tid % 9;
            float acc = 0.f;
            #pragma unroll
            for (int o = 0; o < 8; o++) acc += e1[o] * s.w3s[o * 72 + ci * 9 + tap];
            s.Weff[tid] = acc / d1;
        } else {
            int c = tid - 72;
            float m = (s.Sgp[c][0] + s.Sgp[c][1]) * (1.0f / 4096.0f);
            float q = (s.Sg2p[c][0] + s.Sg2p[c][1]) * (1.0f / 4096.0f);
            float rsg = rsqrtf(q - m * m + 1e-5f);
            float x21 = e2[c] / d2;
            float x11 = e1[c] / d1;
            float gr = s.gnws[c] * rsg;
            s.Aarr[c]  = x21 * gr;
            s.Kpart[c] = x21 * (s.gnbs[c] - gr * m) + x11 * s.b3s[c];
        }
    }
    __syncthreads();

    // ---- F1: scalar fused conv + gated-norm (512 units: 1 row x 8 cols) ----
    {
        int i0 = tid >> 3;               // output row 0..63
        int j0 = (tid & 7) << 3;         // output cols j0..j0+7
        float init = ((s.Kpart[0] + s.Kpart[1]) + (s.Kpart[2] + s.Kpart[3]))
                   + ((s.Kpart[4] + s.Kpart[5]) + (s.Kpart[6] + s.Kpart[7]));
        float acc[8];
        #pragma unroll
        for (int p = 0; p < 8; p++) acc[p] = init;

        #pragma unroll
        for (int ci = 0; ci < 8; ci++) {
            const float* wc = &s.Weff[ci * 9];
            float c0w = wc[0], c1w = wc[1], c2w = wc[2];
            float c3w = wc[3], c4w = wc[4], c5w = wc[5];
            float c6w = wc[6], c7w = wc[7], c8w = wc[8];
            float coef = s.Aarr[ci] * s.sh[ci][i0];
            float4 swa = *(const float4*)&s.sw[ci][j0];
            float4 swb = *(const float4*)&s.sw[ci][j0 + 4];
            float swp[8] = {swa.x, swa.y, swa.z, swa.w, swb.x, swb.y, swb.z, swb.w};
            float w[12];
            ld12(&s.tile[ci][i0][j0], w);
            #pragma unroll
            for (int p = 0; p < 8; p++)
                acc[p] += c0w * w[p + 1] + c1w * w[p + 2] + c2w * w[p + 3];
            ld12(&s.tile[ci][i0 + 1][j0], w);
            #pragma unroll
            for (int p = 0; p < 8; p++)
                acc[p] += c3w * w[p + 1] + c4w * w[p + 2] + c5w * w[p + 3]
                        + coef * swp[p] * w[p + 2];
            ld12(&s.tile[ci][i0 + 2][j0], w);
            #pragma unroll
            for (int p = 0; p < 8; p++)
                acc[p] += c6w * w[p + 1] + c7w * w[p + 2] + c8w * w[p + 3];
        }
        *(float4*)&s.wt[i0 * 64 + j0] =
            make_float4(sigf(acc[0]), sigf(acc[1]), sigf(acc[2]), sigf(acc[3]));
        *(float4*)&s.wt[i0 * 64 + j0 + 4] =
            make_float4(sigf(acc[4]), sigf(acc[5]), sigf(acc[6]), sigf(acc[7]));
    }
    __syncthreads();

    // ---- F2: out = gx(fp32 from L2) * wt ----
    #pragma unroll
    for (int k = 0; k < 16; k++) {
        int l4 = tid + NTH * k;
        int c = l4 >> 10;
        int i = (l4 >> 4) & 63;
        int j4 = (l4 & 15) << 2;
        float4 wv = *(const float4*)&s.wt[i * 64 + j4];
        float4 v = src4[c * 1024 + i * 16 + (j4 >> 2)];
        float4 o4 = make_float4(v.x * wv.x, v.y * wv.y, v.z * wv.z, v.w * wv.w);
        *reinterpret_cast<float4*>(&dst[c * 4096 + i * 64 + j4]) = o4;
    }
}

extern "C" void kernel_launch(void* const* d_in, const int* in_sizes, int n_in,
                              void* d_out, int out_size) {
    (void)in_sizes; (void)n_in; (void)out_size;
    const float* x   = (const float*)d_in[0];
    const float* w1  = (const float*)d_in[1];
    const float* b1  = (const float*)d_in[2];
    const float* w3  = (const float*)d_in[3];
    const float* b3  = (const float*)d_in[4];
    const float* gnw = (const float*)d_in[5];
    const float* gnb = (const float*)d_in[6];
    float* out = (float*)d_out;

    size_t smem = sizeof(SmC);
    cudaFuncSetAttribute(fused_kernel, cudaFuncAttributeMaxDynamicSharedMemorySize, (int)smem);
    fused_kernel<<<1024, NTH, smem>>>(x, w1, b1, w3, b3, gnw, gnb, out);
}

// round 12
// speedup vs baseline: 1.0970x; 1.0970x over previous
#include <cuda_runtime.h>
#include <cuda_fp16.h>
#include <cstdint>
#include <math.h>

#define PWH 72
#define NTH 512

struct SmC {
    unsigned long long mbar[2];
    __half tile[8][34][PWH];   // fp16 padded tile; interior rows 1..32, cols 2..65
    float excol[2][8][64];
    float exedge[2][8];
    float excor[2][8][2];
    float exsg[2][8][2];
    float exsg2[2][8][2];
    float rowsum[8][32];
    float sh[8][32];
    float sw[8][64];
    float accp[2][32][64];     // F1 partial sums (ci 0-3 / ci 4-7)
    float w1s[64];
    float w3s[576];
    float b1s[8], b3s[8], gnws[8], gnbs[8];
    float S2l[8];
    float Aarr[8], Kpart[8];
    float Weff[72];
};

// sigmoid via single-MUFU tanh.approx: sigmoid(x) = 0.5*tanh(0.5x) + 0.5
__device__ __forceinline__ float sigf(float v) {
    float t;
    asm("tanh.approx.f32 %0, %1;" : "=f"(t) : "f"(v * 0.5f));
    return fmaf(t, 0.5f, 0.5f);
}

__device__ __forceinline__ uint32_t s2u(const void* p) {
    uint32_t a;
    asm("{ .reg .u64 t; cvta.to.shared.u64 t, %1; cvt.u32.u64 %0, t; }" : "=r"(a) : "l"(p));
    return a;
}
__device__ __forceinline__ void st_peer(const void* laddr, uint32_t prank, float v) {
    uint32_t la = s2u(laddr);
    uint32_t ra;
    asm volatile("mapa.shared::cluster.u32 %0, %1, %2;" : "=r"(ra) : "r"(la), "r"(prank));
    asm volatile("st.shared::cluster.f32 [%0], %1;" :: "r"(ra), "f"(v) : "memory");
}
__device__ __forceinline__ void st_peer64(const void* laddr, uint32_t prank, unsigned long long v) {
    uint32_t la = s2u(laddr);
    uint32_t ra;
    asm volatile("mapa.shared::cluster.u32 %0, %1, %2;" : "=r"(ra) : "r"(la), "r"(prank));
    asm volatile("st.shared::cluster.b64 [%0], %1;" :: "r"(ra), "l"(v) : "memory");
}
__device__ __forceinline__ unsigned long long pk2(float a, float b) {
    unsigned long long r;
    asm("mov.b64 %0, {%1, %2};" : "=l"(r) : "f"(a), "f"(b));
    return r;
}

__device__ __forceinline__ void mbar_init(const void* p, uint32_t cnt) {
    asm volatile("mbarrier.init.shared.b64 [%0], %1;" :: "r"(s2u(p)), "r"(cnt) : "memory");
}
__device__ __forceinline__ void mbar_arrive_peer(const void* p, uint32_t prank) {
    uint32_t la = s2u(p), ra;
    asm volatile("mapa.shared::cluster.u32 %0, %1, %2;" : "=r"(ra) : "r"(la), "r"(prank));
    asm volatile("mbarrier.arrive.release.cluster.shared::cluster.b64 _, [%0];"
                 :: "r"(ra) : "memory");
}
__device__ __forceinline__ void mbar_wait(const void* p, uint32_t parity) {
    uint32_t la = s2u(p);
    asm volatile(
        "{\n\t.reg .pred P;\n\t"
        "WAITL_%=:\n\t"
        "mbarrier.try_wait.parity.acquire.cluster.shared::cta.b64 P, [%0], %1, 0x989680;\n\t"
        "@P bra.uni WDONE_%=;\n\t"
        "bra.uni WAITL_%=;\n\t"
        "WDONE_%=:\n\t}"
        :: "r"(la), "r"(parity) : "memory");
}

#define CLUSTER_SYNC() do { \
    asm volatile("barrier.cluster.arrive.aligned;" ::: "memory"); \
    asm volatile("barrier.cluster.wait.aligned;" ::: "memory"); \
} while (0)

// load 12 consecutive padded halfs (16B-aligned) -> 12 floats
__device__ __forceinline__ void ld12(const __half* p, float* w) {
    uint4 a = *(const uint4*)p;
    uint2 b = *(const uint2*)(p + 8);
    float2 f;
    f = __half22float2(*(__half2*)&a.x); w[0] = f.x;  w[1] = f.y;
    f = __half22float2(*(__half2*)&a.y); w[2] = f.x;  w[3] = f.y;
    f = __half22float2(*(__half2*)&a.z); w[4] = f.x;  w[5] = f.y;
    f = __half22float2(*(__half2*)&a.w); w[6] = f.x;  w[7] = f.y;
    f = __half22float2(*(__half2*)&b.x); w[8] = f.x;  w[9] = f.y;
    f = __half22float2(*(__half2*)&b.y); w[10] = f.x; w[11] = f.y;
}

__global__ void __launch_bounds__(NTH, 2) __cluster_dims__(2, 1, 1)
fused_kernel(const float* __restrict__ x,
             const float* __restrict__ w1, const float* __restrict__ b1,
             const float* __restrict__ w3, const float* __restrict__ b3,
             const float* __restrict__ gnw, const float* __restrict__ gnb,
             float* __restrict__ out)
{
    extern __shared__ char smraw[];
    SmC& s = *reinterpret_cast<SmC*>(smraw);
    const int tid = threadIdx.x;
    uint32_t rank;
    asm("mov.u32 %0, %%cluster_ctarank;" : "=r"(rank));
    const uint32_t prank = 1u - rank;
    const long long g = blockIdx.x >> 1;
    const int rbase = (int)rank * 32;
    const float* src = x + g * 32768;
    float* dst = out + g * 32768;
    const float4* src4 = reinterpret_cast<const float4*>(src);

    if (tid == 0) {
        mbar_init(&s.mbar[0], 1);
        mbar_init(&s.mbar[1], 1);
    }

    // ---- phase A: borders + params + interior load (fp16 STS) + halo row ----
    {
        const __half hz = __float2half(0.f);
        int outer = (rank == 0) ? 0 : 33;
        for (int t = tid; t < 8 * 408; t += NTH) {
            int c = t / 408;
            int u = t % 408;
            if (u < 72) {
                s.tile[c][outer][u] = hz;
            } else {
                int u2 = u - 72;
                int r = u2 >> 3;
                int row = (rank == 0) ? (r + 1) : r;
                int m = u2 & 7;
                int col = (m < 2) ? m : (64 + m);
                s.tile[c][row][col] = hz;
            }
        }
    }
    if (tid < 64) s.w1s[tid] = w1[tid];
    if (tid >= 64 && tid < 72) {
        int c = tid - 64;
        s.b1s[c] = b1[c]; s.b3s[c] = b3[c];
        s.gnws[c] = gnw[c]; s.gnbs[c] = gnb[c];
    }
    for (int t = tid; t < 576; t += NTH) s.w3s[t] = w3[t];

    {
        int i = (tid >> 4) & 31;
        int j4 = (tid & 15) << 2;
        #pragma unroll
        for (int c = 0; c < 8; c++) {
            float4 v = src4[c * 1024 + (rbase + i) * 16 + (j4 >> 2)];
            __half2* p = (__half2*)&s.tile[c][i + 1][j4 + 2];
            p[0] = __floats2half2_rn(v.x, v.y);
            p[1] = __floats2half2_rn(v.z, v.w);
        }
    }
    if (tid < 128) {
        int c = tid >> 4;
        int j4 = (tid & 15) << 2;
        int grow = (rank == 0) ? 32 : 31;
        int prow = (rank == 0) ? 33 : 0;
        float4 v = src4[c * 1024 + grow * 16 + (j4 >> 2)];
        __half2* p = (__half2*)&s.tile[c][prow][j4 + 2];
        p[0] = __floats2half2_rn(v.x, v.y);
        p[1] = __floats2half2_rn(v.z, v.w);
    }
    __syncthreads();
    CLUSTER_SYNC();   // orders mbarrier init across the cluster (L1 cold; flush harmless)

    // ---- phase B: rowsums (HADD2) + colsum partials (half2) + edges + corners ----
    {
        int t = tid;
        if (t < 256) {
            int c = t >> 5, i = t & 31;
            const uint4* rp = reinterpret_cast<const uint4*>(&s.tile[c][i + 1][0]);
            __half2 a0 = __float2half2_rn(0.f), a1 = a0, a2 = a0, a3 = a0;
            #pragma unroll
            for (int q = 0; q < 9; q++) {
                uint4 u = rp[q];
                a0 = __hadd2(a0, *(__half2*)&u.x);
                a1 = __hadd2(a1, *(__half2*)&u.y);
                a2 = __hadd2(a2, *(__half2*)&u.z);
                a3 = __hadd2(a3, *(__half2*)&u.w);
            }
            __half2 hs = __hadd2(__hadd2(a0, a1), __hadd2(a2, a3));
            float2 f = __half22float2(hs);
            float rsum = f.x + f.y;
            s.rowsum[c][i] = rsum;
            int edgei = (rank == 0) ? 0 : 31;
            if (i == edgei) {
                s.exedge[rank][c] = rsum;
                st_peer(&s.exedge[rank][c], prank, rsum);
            }
        } else {
            int u = t - 256;
            int c = u >> 5, jp = u & 31;     // columns 2jp, 2jp+1
            const __half2* cp = (const __half2*)&s.tile[c][1][2 + 2 * jp];
            __half2 a0 = __float2half2_rn(0.f), a1 = a0;
            #pragma unroll
            for (int r = 0; r < 32; r += 2) {
                a0 = __hadd2(a0, cp[r * (PWH / 2)]);
                a1 = __hadd2(a1, cp[(r + 1) * (PWH / 2)]);
            }
            float2 f = __half22float2(__hadd2(a0, a1));
            *(float2*)&s.excol[rank][c][2 * jp] = f;
            st_peer64(&s.excol[rank][c][2 * jp], prank, pk2(f.x, f.y));
        }
    }
    if (tid < 8) {
        int c = tid;
        float a, b;
        if (rank == 0) { a = __half2float(s.tile[c][1][2]);  b = __half2float(s.tile[c][1][65]); }
        else           { a = __half2float(s.tile[c][32][2]); b = __half2float(s.tile[c][32][65]); }
        s.excor[rank][c][0] = a;
        s.excor[rank][c][1] = b;
        st_peer(&s.excor[rank][c][0], prank, a);
        st_peer(&s.excor[rank][c][1], prank, b);
    }
    __syncthreads();
    if (tid == 0) mbar_arrive_peer(&s.mbar[0], prank);
    mbar_wait(&s.mbar[0], 0);

    // ---- phase C: sh + sw; warp0 additionally computes T (shfl) + S2l ----
    {
        const float inv = 1.0f / 64.0f;
        int t = tid;
        if (t < 256) {
            int o = t >> 5, i = t & 31;
            float acc = s.b1s[o];
            #pragma unroll
            for (int c = 0; c < 8; c++) acc += s.w1s[o * 8 + c] * (s.rowsum[c][i] * inv);
            s.sh[o][i] = sigf(acc);
        } else {
            int u = t - 256;
            int o = u >> 5;
            int v = u & 31;
            int j = 2 * v;
            int j2 = j + 1;
            float acc = s.b1s[o], acc2 = s.b1s[o];
            #pragma unroll
            for (int c = 0; c < 8; c++) {
                float cma = s.excol[0][c][j]  + s.excol[1][c][j];
                float cmb = s.excol[0][c][j2] + s.excol[1][c][j2];
                float wv = s.w1s[o * 8 + c];
                acc  += wv * (cma * inv);
                acc2 += wv * (cmb * inv);
            }
            s.sw[o][j]  = sigf(acc);
            s.sw[o][j2] = sigf(acc2);
        }
    }
    if (tid < 32) {
        int lane = tid;
        int c = lane & 7;
        float Tc = 0.f;
        if (lane < 8) {
            // bank-rotated sum of excol over both ranks
            float a0 = 0.f, a1 = 0.f, a2 = 0.f, a3 = 0.f;
            int base = (c * 4) & 63;
            #pragma unroll
            for (int j = 0; j < 64; j += 4) {
                int jj = (base + j) & 63;
                a0 += s.excol[0][c][jj]     + s.excol[1][c][jj];
                a1 += s.excol[0][c][jj + 1] + s.excol[1][c][jj + 1];
                a2 += s.excol[0][c][jj + 2] + s.excol[1][c][jj + 2];
                a3 += s.excol[0][c][jj + 3] + s.excol[1][c][jj + 3];
            }
            Tc = (a0 + a1) + (a2 + a3);
        }
        float acc = 0.f;
        #pragma unroll
        for (int ci = 0; ci < 8; ci++) {
            float T = __shfl_sync(0xffffffffu, Tc, ci);
            if (lane < 8) {
                float r0  = s.exedge[0][ci], r63 = s.exedge[1][ci];
                float c0  = s.excol[0][ci][0]  + s.excol[1][ci][0];
                float c63 = s.excol[0][ci][63] + s.excol[1][ci][63];
                float g00 = s.excor[0][ci][0], g0e = s.excor[0][ci][1];
                float ge0 = s.excor[1][ci][0], gee = s.excor[1][ci][1];
                float Sv[9];
                Sv[0] = T - r63 - c63 + gee;
                Sv[1] = T - r63;
                Sv[2] = T - r63 - c0 + ge0;
                Sv[3] = T - c63;
                Sv[4] = T;
                Sv[5] = T - c0;
                Sv[6] = T - r0 - c63 + g0e;
                Sv[7] = T - r0;
                Sv[8] = T - r0 - c0 + g00;
                const float* wp = &s.w3s[c * 72 + ci * 9];
                #pragma unroll
                for (int k = 0; k < 9; k++) acc += wp[k] * Sv[k];
            }
        }
        if (lane < 8)
            s.S2l[c] = acc * (1.0f / 4096.0f) + s.b3s[c];
    }
    __syncthreads();

    // ---- phase D: gated stats (16 warps), exchange partials ----
    {
        int w = tid >> 5;
        int c = w >> 1;
        int half = w & 1;
        int lane = tid & 31;
        float2 swp = *(const float2*)&s.sw[c][2 * lane];
        float s0 = 0.f, s1 = 0.f, q0 = 0.f, q1 = 0.f;
        int ibase = half * 16;
        #pragma unroll 4
        for (int r = 0; r < 16; r++) {
            int i = ibase + r;
            float shi = s.sh[c][i];
            __half2 h = *(const __half2*)&s.tile[c][i + 1][2 + 2 * lane];
            float2 gf = __half22float2(h);
            float v0 = gf.x * (shi * swp.x);
            float v1 = gf.y * (shi * swp.y);
            s0 += v0; s1 += v1;
            q0 += v0 * v0; q1 += v1 * v1;
        }
        float sum = s0 + s1, sq = q0 + q1;
        #pragma unroll
        for (int off = 16; off; off >>= 1) {
            sum += __shfl_xor_sync(0xffffffffu, sum, off);
            sq  += __shfl_xor_sync(0xffffffffu, sq,  off);
        }
        if (lane == 0) {
            s.exsg[rank][c][half] = sum;  s.exsg2[rank][c][half] = sq;
            st_peer(&s.exsg[rank][c][half],  prank, sum);
            st_peer(&s.exsg2[rank][c][half], prank, sq);
        }
    }
    __syncthreads();
    if (tid == 0) mbar_arrive_peer(&s.mbar[1], prank);
    mbar_wait(&s.mbar[1], 0);

    // ---- phase E: redundant softmaxes (80 threads) -> Weff / Aarr / Kpart ----
    if (tid < 80) {
        float mx1 = -1e30f, mx2 = -1e30f;
        #pragma unroll
        for (int k = 0; k < 8; k++) {
            mx1 = fmaxf(mx1, s.gnbs[k]);
            mx2 = fmaxf(mx2, s.S2l[k]);
        }
        float e1[8], e2[8];
        float d1 = 0.f, d2 = 0.f;
        #pragma unroll
        for (int k = 0; k < 8; k++) {
            e1[k] = __expf(s.gnbs[k] - mx1); d1 += e1[k];
            e2[k] = __expf(s.S2l[k] - mx2);  d2 += e2[k];
        }
        if (tid < 72) {
            int ci = tid / 9, tap = tid % 9;
            float acc = 0.f;
            #pragma unroll
            for (int o = 0; o < 8; o++) acc += e1[o] * s.w3s[o * 72 + ci * 9 + tap];
            s.Weff[tid] = acc / d1;
        } else {
            int c = tid - 72;
            float m = (s.exsg[0][c][0] + s.exsg[0][c][1]
                     + s.exsg[1][c][0] + s.exsg[1][c][1]) * (1.0f / 4096.0f);
            float q = (s.exsg2[0][c][0] + s.exsg2[0][c][1]
                     + s.exsg2[1][c][0] + s.exsg2[1][c][1]) * (1.0f / 4096.0f);
            float rsg = rsqrtf(q - m * m + 1e-5f);
            float x21 = e2[c] / d2;
            float x11 = e1[c] / d1;
            float gr = s.gnws[c] * rsg;
            s.Aarr[c]  = x21 * gr;
            s.Kpart[c] = x21 * (s.gnbs[c] - gr * m) + x11 * s.b3s[c];
        }
    }
    __syncthreads();

    // ---- F1: scalar fused conv + gated-norm, split over ci halves ----
    {
        int half = tid >> 8;             // 0: ci 0-3, 1: ci 4-7
        int unit = tid & 255;
        int i0 = unit >> 3;              // local output row 0..31
        int j0 = (unit & 7) << 3;        // output cols j0..j0+7
        int cibase = half << 2;
        float acc[8];
        float init = 0.f;
        if (half == 0) {
            init = ((s.Kpart[0] + s.Kpart[1]) + (s.Kpart[2] + s.Kpart[3]))
                 + ((s.Kpart[4] + s.Kpart[5]) + (s.Kpart[6] + s.Kpart[7]));
        }
        #pragma unroll
        for (int p = 0; p < 8; p++) acc[p] = init;

        #pragma unroll
        for (int cq = 0; cq < 4; cq++) {
            int ci = cibase + cq;
            const float* wc = &s.Weff[ci * 9];
            float c0w = wc[0], c1w = wc[1], c2w = wc[2];
            float c3w = wc[3], c4w = wc[4], c5w = wc[5];
            float c6w = wc[6], c7w = wc[7], c8w = wc[8];
            float coef = s.Aarr[ci] * s.sh[ci][i0];
            float4 swa = *(const float4*)&s.sw[ci][j0];
            float4 swb = *(const float4*)&s.sw[ci][j0 + 4];
            float swp[8] = {swa.x, swa.y, swa.z, swa.w, swb.x, swb.y, swb.z, swb.w};
            float w[12];
            ld12(&s.tile[ci][i0][j0], w);
            #pragma unroll
            for (int p = 0; p < 8; p++)
                acc[p] += c0w * w[p + 1] + c1w * w[p + 2] + c2w * w[p + 3];
            ld12(&s.tile[ci][i0 + 1][j0], w);
            #pragma unroll
            for (int p = 0; p < 8; p++)
                acc[p] += c3w * w[p + 1] + c4w * w[p + 2] + c5w * w[p + 3]
                        + coef * swp[p] * w[p + 2];
            ld12(&s.tile[ci][i0 + 2][j0], w);
            #pragma unroll
            for (int p = 0; p < 8; p++)
                acc[p] += c6w * w[p + 1] + c7w * w[p + 2] + c8w * w[p + 3];
        }
        *(float4*)&s.accp[half][i0][j0] =
            make_float4(acc[0], acc[1], acc[2], acc[3]);
        *(float4*)&s.accp[half][i0][j0 + 4] =
            make_float4(acc[4], acc[5], acc[6], acc[7]);
    }
    __syncthreads();

    // ---- F2: wt = sigmoid(acc0+acc1); out = gx(fp16 tile) * wt ----
    {
        int i = (tid >> 4) & 31;
        int j4 = (tid & 15) << 2;
        float4 p0 = *(const float4*)&s.accp[0][i][j4];
        float4 p1 = *(const float4*)&s.accp[1][i][j4];
        float4 wv = make_float4(sigf(p0.x + p1.x), sigf(p0.y + p1.y),
                                sigf(p0.z + p1.z), sigf(p0.w + p1.w));
        #pragma unroll
        for (int c = 0; c < 8; c++) {
            __half2 ha = *(const __half2*)&s.tile[c][i + 1][j4 + 2];
            __half2 hb = *(const __half2*)&s.tile[c][i + 1][j4 + 4];
            float2 fa = __half22float2(ha);
            float2 fb = __half22float2(hb);
            float4 o4 = make_float4(fa.x * wv.x, fa.y * wv.y, fb.x * wv.z, fb.y * wv.w);
            *reinterpret_cast<float4*>(&dst[c * 4096 + (rbase + i) * 64 + j4]) = o4;
        }
    }
}

extern "C" void kernel_launch(void* const* d_in, const int* in_sizes, int n_in,
                              void* d_out, int out_size) {
    (void)in_sizes; (void)n_in; (void)out_size;
    const float* x   = (const float*)d_in[0];
    const float* w1  = (const float*)d_in[1];
    const float* b1  = (const float*)d_in[2];
    const float* w3  = (const float*)d_in[3];
    const float* b3  = (const float*)d_in[4];
    const float* gnw = (const float*)d_in[5];
    const float* gnb = (const float*)d_in[6];
    float* out = (float*)d_out;

    size_t smem = sizeof(SmC);
    cudaFuncSetAttribute(fused_kernel, cudaFuncAttributeMaxDynamicSharedMemorySize, (int)smem);
    fused_kernel<<<2048, NTH, smem>>>(x, w1, b1, w3, b3, gnw, gnb, out);
}

// round 13
// speedup vs baseline: 1.1536x; 1.0516x over previous
#include <cuda_runtime.h>
#include <cuda_fp16.h>
#include <cstdint>
#include <math.h>

#define PWH 72
#define NTH 512

struct SmC {
    __half tile[8][34][PWH];   // fp16 padded tile; interior rows 1..32, cols 2..65
    float excol[2][8][64];
    float colm[8][64];
    float exedge[2][8];
    float excor[2][8][2];
    float exsg[2][8][2];
    float exsg2[2][8][2];
    float rowsum[8][32];
    float sh[8][32];
    float sw[8][64];
    float accp[2][32][64];     // F1 partial sums (ci 0-3 / ci 4-7)
    float w1s[64];
    float w3s[576];
    float b1s[8], b3s[8], gnws[8], gnbs[8];
    float S2l[8];
    float Aarr[8], Kpart[8];
    float Weff[72];
};

__device__ __forceinline__ float sigf(float v) {
    return 1.0f / (1.0f + __expf(-v));
}

__device__ __forceinline__ uint32_t s2u(const void* p) {
    uint32_t a;
    asm("{ .reg .u64 t; cvta.to.shared.u64 t, %1; cvt.u32.u64 %0, t; }" : "=r"(a) : "l"(p));
    return a;
}
__device__ __forceinline__ void st_peer(const void* laddr, uint32_t prank, float v) {
    uint32_t la = s2u(laddr);
    uint32_t ra;
    asm volatile("mapa.shared::cluster.u32 %0, %1, %2;" : "=r"(ra) : "r"(la), "r"(prank));
    asm volatile("st.shared::cluster.f32 [%0], %1;" :: "r"(ra), "f"(v) : "memory");
}
__device__ __forceinline__ void st_peer64(const void* laddr, uint32_t prank, unsigned long long v) {
    uint32_t la = s2u(laddr);
    uint32_t ra;
    asm volatile("mapa.shared::cluster.u32 %0, %1, %2;" : "=r"(ra) : "r"(la), "r"(prank));
    asm volatile("st.shared::cluster.b64 [%0], %1;" :: "r"(ra), "l"(v) : "memory");
}
__device__ __forceinline__ unsigned long long pk2(float a, float b) {
    unsigned long long r;
    asm("mov.b64 %0, {%1, %2};" : "=l"(r) : "f"(a), "f"(b));
    return r;
}

#define CLUSTER_SYNC() do { \
    asm volatile("barrier.cluster.arrive.aligned;" ::: "memory"); \
    asm volatile("barrier.cluster.wait.aligned;" ::: "memory"); \
} while (0)

// load 12 consecutive padded halfs (16B-aligned) -> 12 floats
__device__ __forceinline__ void ld12(const __half* p, float* w) {
    uint4 a = *(const uint4*)p;
    uint2 b = *(const uint2*)(p + 8);
    float2 f;
    f = __half22float2(*(__half2*)&a.x); w[0] = f.x;  w[1] = f.y;
    f = __half22float2(*(__half2*)&a.y); w[2] = f.x;  w[3] = f.y;
    f = __half22float2(*(__half2*)&a.z); w[4] = f.x;  w[5] = f.y;
    f = __half22float2(*(__half2*)&a.w); w[6] = f.x;  w[7] = f.y;
    f = __half22float2(*(__half2*)&b.x); w[8] = f.x;  w[9] = f.y;
    f = __half22float2(*(__half2*)&b.y); w[10] = f.x; w[11] = f.y;
}

__global__ void __launch_bounds__(NTH, 2) __cluster_dims__(2, 1, 1)
fused_kernel(const float* __restrict__ x,
             const float* __restrict__ w1, const float* __restrict__ b1,
             const float* __restrict__ w3, const float* __restrict__ b3,
             const float* __restrict__ gnw, const float* __restrict__ gnb,
             float* __restrict__ out)
{
    extern __shared__ char smraw[];
    SmC& s = *reinterpret_cast<SmC*>(smraw);
    const int tid = threadIdx.x;
    uint32_t rank;
    asm("mov.u32 %0, %%cluster_ctarank;" : "=r"(rank));
    const uint32_t prank = 1u - rank;
    const long long g = blockIdx.x >> 1;
    const int rbase = (int)rank * 32;
    const float* src = x + g * 32768;
    float* dst = out + g * 32768;
    const float4* src4 = reinterpret_cast<const float4*>(src);

    // ---- phase A: borders + params + interior load (fp16 STS) + halo row ----
    {
        const __half hz = __float2half(0.f);
        int outer = (rank == 0) ? 0 : 33;
        for (int t = tid; t < 8 * 408; t += NTH) {
            int c = t / 408;
            int u = t % 408;
            if (u < 72) {
                s.tile[c][outer][u] = hz;
            } else {
                int u2 = u - 72;
                int r = u2 >> 3;
                int row = (rank == 0) ? (r + 1) : r;
                int m = u2 & 7;
                int col = (m < 2) ? m : (64 + m);
                s.tile[c][row][col] = hz;
            }
        }
    }
    if (tid < 64) s.w1s[tid] = w1[tid];
    if (tid >= 64 && tid < 72) {
        int c = tid - 64;
        s.b1s[c] = b1[c]; s.b3s[c] = b3[c];
        s.gnws[c] = gnw[c]; s.gnbs[c] = gnb[c];
    }
    for (int t = tid; t < 576; t += NTH) s.w3s[t] = w3[t];

    {
        int i = (tid >> 4) & 31;
        int j4 = (tid & 15) << 2;
        #pragma unroll
        for (int c = 0; c < 8; c++) {
            float4 v = src4[c * 1024 + (rbase + i) * 16 + (j4 >> 2)];
            __half2* p = (__half2*)&s.tile[c][i + 1][j4 + 2];
            p[0] = __floats2half2_rn(v.x, v.y);
            p[1] = __floats2half2_rn(v.z, v.w);
        }
    }
    if (tid < 128) {
        int c = tid >> 4;
        int j4 = (tid & 15) << 2;
        int grow = (rank == 0) ? 32 : 31;
        int prow = (rank == 0) ? 33 : 0;
        float4 v = src4[c * 1024 + grow * 16 + (j4 >> 2)];
        __half2* p = (__half2*)&s.tile[c][prow][j4 + 2];
        p[0] = __floats2half2_rn(v.x, v.y);
        p[1] = __floats2half2_rn(v.z, v.w);
    }
    __syncthreads();

    // ---- phase B: rowsums (HADD2) + colsum partials (half2) + edges + corners ----
    {
        int t = tid;
        if (t < 256) {
            int c = t >> 5, i = t & 31;
            const uint4* rp = reinterpret_cast<const uint4*>(&s.tile[c][i + 1][0]);
            __half2 a0 = __float2half2_rn(0.f), a1 = a0, a2 = a0, a3 = a0;
            #pragma unroll
            for (int q = 0; q < 9; q++) {
                uint4 u = rp[q];
                a0 = __hadd2(a0, *(__half2*)&u.x);
                a1 = __hadd2(a1, *(__half2*)&u.y);
                a2 = __hadd2(a2, *(__half2*)&u.z);
                a3 = __hadd2(a3, *(__half2*)&u.w);
            }
            __half2 hs = __hadd2(__hadd2(a0, a1), __hadd2(a2, a3));
            float2 f = __half22float2(hs);
            float rsum = f.x + f.y;
            s.rowsum[c][i] = rsum;
            int edgei = (rank == 0) ? 0 : 31;
            if (i == edgei) {
                s.exedge[rank][c] = rsum;
                st_peer(&s.exedge[rank][c], prank, rsum);
            }
        } else {
            int u = t - 256;
            int c = u >> 5, jp = u & 31;     // columns 2jp, 2jp+1
            const __half2* cp = (const __half2*)&s.tile[c][1][2 + 2 * jp];
            __half2 a0 = __float2half2_rn(0.f), a1 = a0;
            #pragma unroll
            for (int r = 0; r < 32; r += 2) {
                a0 = __hadd2(a0, cp[r * (PWH / 2)]);
                a1 = __hadd2(a1, cp[(r + 1) * (PWH / 2)]);
            }
            float2 f = __half22float2(__hadd2(a0, a1));
            *(float2*)&s.excol[rank][c][2 * jp] = f;
            st_peer64(&s.excol[rank][c][2 * jp], prank, pk2(f.x, f.y));
        }
    }
    if (tid < 8) {
        int c = tid;
        float a, b;
        if (rank == 0) { a = __half2float(s.tile[c][1][2]);  b = __half2float(s.tile[c][1][65]); }
        else           { a = __half2float(s.tile[c][32][2]); b = __half2float(s.tile[c][32][65]); }
        s.excor[rank][c][0] = a;
        s.excor[rank][c][1] = b;
        st_peer(&s.excor[rank][c][0], prank, a);
        st_peer(&s.excor[rank][c][1], prank, b);
    }
    CLUSTER_SYNC();

    // ---- phase C (single pass): sh + sw (2 cols per unit) ----
    {
        const float inv = 1.0f / 64.0f;
        int t = tid;
        if (t < 256) {
            int o = t >> 5, i = t & 31;
            float acc = s.b1s[o];
            #pragma unroll
            for (int c = 0; c < 8; c++) acc += s.w1s[o * 8 + c] * (s.rowsum[c][i] * inv);
            s.sh[o][i] = sigf(acc);
        } else {
            int u = t - 256;
            int o = u >> 5;
            int v = u & 31;
            int j = 2 * v;
            int j2 = j + 1;
            float acc = s.b1s[o], acc2 = s.b1s[o];
            #pragma unroll
            for (int c = 0; c < 8; c++) {
                float cma = s.excol[0][c][j]  + s.excol[1][c][j];
                float cmb = s.excol[0][c][j2] + s.excol[1][c][j2];
                if (o == 0) { s.colm[c][j] = cma; s.colm[c][j2] = cmb; }
                float wv = s.w1s[o * 8 + c];
                acc  += wv * (cma * inv);
                acc2 += wv * (cmb * inv);
            }
            s.sw[o][j]  = sigf(acc);
            s.sw[o][j2] = sigf(acc2);
        }
    }
    __syncthreads();

    // ---- phase D: gated stats (16 warps) + warp0: T via shfl + S2l (no extra sync) ----
    {
        int w = tid >> 5;
        int c = w >> 1;
        int half = w & 1;
        int lane = tid & 31;
        float2 swp = *(const float2*)&s.sw[c][2 * lane];
        float s0 = 0.f, s1 = 0.f, q0 = 0.f, q1 = 0.f;
        int ibase = half * 16;
        #pragma unroll 4
        for (int r = 0; r < 16; r++) {
            int i = ibase + r;
            float shi = s.sh[c][i];
            __half2 h = *(const __half2*)&s.tile[c][i + 1][2 + 2 * lane];
            float2 gf = __half22float2(h);
            float v0 = gf.x * (shi * swp.x);
            float v1 = gf.y * (shi * swp.y);
            s0 += v0; s1 += v1;
            q0 += v0 * v0; q1 += v1 * v1;
        }
        float sum = s0 + s1, sq = q0 + q1;
        #pragma unroll
        for (int off = 16; off; off >>= 1) {
            sum += __shfl_xor_sync(0xffffffffu, sum, off);
            sq  += __shfl_xor_sync(0xffffffffu, sq,  off);
        }
        if (lane == 0) {
            s.exsg[rank][c][half] = sum;  s.exsg2[rank][c][half] = sq;
            st_peer(&s.exsg[rank][c][half],  prank, sum);
            st_peer(&s.exsg2[rank][c][half], prank, sq);
        }
    }
    if (tid < 32) {
        int lane = tid;
        int c = lane & 7;
        float Tc = 0.f;
        if (lane < 8) {
            float a0 = 0.f, a1 = 0.f, a2 = 0.f, a3 = 0.f;
            int base = (c * 4) & 63;    // bank rotation
            #pragma unroll
            for (int j = 0; j < 64; j += 4) {
                int jj = (base + j) & 63;
                a0 += s.colm[c][jj];     a1 += s.colm[c][jj + 1];
                a2 += s.colm[c][jj + 2]; a3 += s.colm[c][jj + 3];
            }
            Tc = (a0 + a1) + (a2 + a3);
        }
        float acc = 0.f;
        #pragma unroll
        for (int ci = 0; ci < 8; ci++) {
            float T = __shfl_sync(0xffffffffu, Tc, ci);
            if (lane < 8) {
                float r0  = s.exedge[0][ci], r63 = s.exedge[1][ci];
                float c0  = s.colm[ci][0],   c63 = s.colm[ci][63];
                float g00 = s.excor[0][ci][0], g0e = s.excor[0][ci][1];
                float ge0 = s.excor[1][ci][0], gee = s.excor[1][ci][1];
                float Sv[9];
                Sv[0] = T - r63 - c63 + gee;
                Sv[1] = T - r63;
                Sv[2] = T - r63 - c0 + ge0;
                Sv[3] = T - c63;
                Sv[4] = T;
                Sv[5] = T - c0;
                Sv[6] = T - r0 - c63 + g0e;
                Sv[7] = T - r0;
                Sv[8] = T - r0 - c0 + g00;
                const float* wp = &s.w3s[c * 72 + ci * 9];
                #pragma unroll
                for (int k = 0; k < 9; k++) acc += wp[k] * Sv[k];
            }
        }
        if (lane < 8)
            s.S2l[c] = acc * (1.0f / 4096.0f) + s.b3s[c];
    }
    CLUSTER_SYNC();

    // ---- phase E: redundant softmaxes (80 threads) -> Weff / Aarr / Kpart ----
    if (tid < 80) {
        float mx1 = -1e30f, mx2 = -1e30f;
        #pragma unroll
        for (int k = 0; k < 8; k++) {
            mx1 = fmaxf(mx1, s.gnbs[k]);
            mx2 = fmaxf(mx2, s.S2l[k]);
        }
        float e1[8], e2[8];
        float d1 = 0.f, d2 = 0.f;
        #pragma unroll
        for (int k = 0; k < 8; k++) {
            e1[k] = __expf(s.gnbs[k] - mx1); d1 += e1[k];
            e2[k] = __expf(s.S2l[k] - mx2);  d2 += e2[k];
        }
        if (tid < 72) {
            int ci = tid / 9, tap = tid % 9;
            float acc = 0.f;
            #pragma unroll
            for (int o = 0; o < 8; o++) acc += e1[o] * s.w3s[o * 72 + ci * 9 + tap];
            s.Weff[tid] = acc / d1;
        } else {
            int c = tid - 72;
            float m = (s.exsg[0][c][0] + s.exsg[0][c][1]
                     + s.exsg[1][c][0] + s.exsg[1][c][1]) * (1.0f / 4096.0f);
            float q = (s.exsg2[0][c][0] + s.exsg2[0][c][1]
                     + s.exsg2[1][c][0] + s.exsg2[1][c][1]) * (1.0f / 4096.0f);
            float rsg = rsqrtf(q - m * m + 1e-5f);
            float x21 = e2[c] / d2;
            float x11 = e1[c] / d1;
            float gr = s.gnws[c] * rsg;
            s.Aarr[c]  = x21 * gr;
            s.Kpart[c] = x21 * (s.gnbs[c] - gr * m) + x11 * s.b3s[c];
        }
    }
    __syncthreads();

    // ---- F1: scalar fused conv + gated-norm, split over ci halves ----
    {
        int half = tid >> 8;             // 0: ci 0-3, 1: ci 4-7
        int unit = tid & 255;
        int i0 = unit >> 3;              // local output row 0..31
        int j0 = (unit & 7) << 3;        // output cols j0..j0+7
        int cibase = half << 2;
        float acc[8];
        float init = 0.f;
        if (half == 0) {
            init = ((s.Kpart[0] + s.Kpart[1]) + (s.Kpart[2] + s.Kpart[3]))
                 + ((s.Kpart[4] + s.Kpart[5]) + (s.Kpart[6] + s.Kpart[7]));
        }
        #pragma unroll
        for (int p = 0; p < 8; p++) acc[p] = init;

        #pragma unroll
        for (int cq = 0; cq < 4; cq++) {
            int ci = cibase + cq;
            const float* wc = &s.Weff[ci * 9];
            float c0w = wc[0], c1w = wc[1], c2w = wc[2];
            float c3w = wc[3], c4w = wc[4], c5w = wc[5];
            float c6w = wc[6], c7w = wc[7], c8w = wc[8];
            float coef = s.Aarr[ci] * s.sh[ci][i0];
            float4 swa = *(const float4*)&s.sw[ci][j0];
            float4 swb = *(const float4*)&s.sw[ci][j0 + 4];
            float swp[8] = {swa.x, swa.y, swa.z, swa.w, swb.x, swb.y, swb.z, swb.w};
            float w[12];
            ld12(&s.tile[ci][i0][j0], w);
            #pragma unroll
            for (int p = 0; p < 8; p++)
                acc[p] += c0w * w[p + 1] + c1w * w[p + 2] + c2w * w[p + 3];
            ld12(&s.tile[ci][i0 + 1][j0], w);
            #pragma unroll
            for (int p = 0; p < 8; p++)
                acc[p] += c3w * w[p + 1] + c4w * w[p + 2] + c5w * w[p + 3]
                        + coef * swp[p] * w[p + 2];
            ld12(&s.tile[ci][i0 + 2][j0], w);
            #pragma unroll
            for (int p = 0; p < 8; p++)
                acc[p] += c6w * w[p + 1] + c7w * w[p + 2] + c8w * w[p + 3];
        }
        *(float4*)&s.accp[half][i0][j0] =
            make_float4(acc[0], acc[1], acc[2], acc[3]);
        *(float4*)&s.accp[half][i0][j0 + 4] =
            make_float4(acc[4], acc[5], acc[6], acc[7]);
    }
    __syncthreads();

    // ---- F2: wt = sigmoid(acc0+acc1); out = gx(fp16 tile) * wt ----
    {
        int i = (tid >> 4) & 31;
        int j4 = (tid & 15) << 2;
        float4 p0 = *(const float4*)&s.accp[0][i][j4];
        float4 p1 = *(const float4*)&s.accp[1][i][j4];
        float4 wv = make_float4(sigf(p0.x + p1.x), sigf(p0.y + p1.y),
                                sigf(p0.z + p1.z), sigf(p0.w + p1.w));
        #pragma unroll
        for (int c = 0; c < 8; c++) {
            __half2 ha = *(const __half2*)&s.tile[c][i + 1][j4 + 2];
            __half2 hb = *(const __half2*)&s.tile[c][i + 1][j4 + 4];
            float2 fa = __half22float2(ha);
            float2 fb = __half22float2(hb);
            float4 o4 = make_float4(fa.x * wv.x, fa.y * wv.y, fb.x * wv.z, fb.y * wv.w);
            *reinterpret_cast<float4*>(&dst[c * 4096 + (rbase + i) * 64 + j4]) = o4;
        }
    }
}

extern "C" void kernel_launch(void* const* d_in, const int* in_sizes, int n_in,
                              void* d_out, int out_size) {
    (void)in_sizes; (void)n_in; (void)out_size;
    const float* x   = (const float*)d_in[0];
    const float* w1  = (const float*)d_in[1];
    const float* b1  = (const float*)d_in[2];
    const float* w3  = (const float*)d_in[3];
    const float* b3  = (const float*)d_in[4];
    const float* gnw = (const float*)d_in[5];
    const float* gnb = (const float*)d_in[6];
    float* out = (float*)d_out;

    size_t smem = sizeof(SmC);
    cudaFuncSetAttribute(fused_kernel, cudaFuncAttributeMaxDynamicSharedMemorySize, (int)smem);
    fused_kernel<<<2048, NTH, smem>>>(x, w1, b1, w3, b3, gnw, gnb, out);
}

// round 15
// speedup vs baseline: 1.1645x; 1.0094x over previous
#include <cuda_runtime.h>
#include <cuda_fp16.h>
#include <cstdint>
#include <math.h>

#define PWH 72
#define NTH 512

struct SmC {
    __half tile[8][34][PWH];   // fp16 padded tile; interior rows 1..32, cols 2..65
    float excol[2][8][64];
    float colm[8][64];
    float exedge[2][8];
    float excor[2][8][2];
    float exsg[2][8][2];
    float exsg2[2][8][2];
    float rowsum[8][32];
    float sh[8][32];
    float sw[8][64];
    float accp[4][32][64];     // F1 partial sums (ci pairs 01/23/45/67)
    float w1s[64];             // pre-scaled by 1/64
    float w3s[576];
    float b1s[8], b3s[8], gnws[8], gnbs[8];
    float S2l[8];
    float Aarr[8], Kpart[8];
    float Weff[72];
};

__device__ __forceinline__ float sigf(float v) {
    return 1.0f / (1.0f + __expf(-v));
}

__device__ __forceinline__ uint32_t s2u(const void* p) {
    uint32_t a;
    asm("{ .reg .u64 t; cvta.to.shared.u64 t, %1; cvt.u32.u64 %0, t; }" : "=r"(a) : "l"(p));
    return a;
}
__device__ __forceinline__ void st_peer(const void* laddr, uint32_t prank, float v) {
    uint32_t la = s2u(laddr);
    uint32_t ra;
    asm volatile("mapa.shared::cluster.u32 %0, %1, %2;" : "=r"(ra) : "r"(la), "r"(prank));
    asm volatile("st.shared::cluster.f32 [%0], %1;" :: "r"(ra), "f"(v) : "memory");
}
__device__ __forceinline__ void st_peer64(const void* laddr, uint32_t prank, unsigned long long v) {
    uint32_t la = s2u(laddr);
    uint32_t ra;
    asm volatile("mapa.shared::cluster.u32 %0, %1, %2;" : "=r"(ra) : "r"(la), "r"(prank));
    asm volatile("st.shared::cluster.b64 [%0], %1;" :: "r"(ra), "l"(v) : "memory");
}
__device__ __forceinline__ unsigned long long pk2(float a, float b) {
    unsigned long long r;
    asm("mov.b64 %0, {%1, %2};" : "=l"(r) : "f"(a), "f"(b));
    return r;
}

#define CLUSTER_SYNC() do { \
    asm volatile("barrier.cluster.arrive.aligned;" ::: "memory"); \
    asm volatile("barrier.cluster.wait.aligned;" ::: "memory"); \
} while (0)

// load 12 consecutive padded halfs (16B-aligned) -> 12 floats
__device__ __forceinline__ void ld12(const __half* p, float* w) {
    uint4 a = *(const uint4*)p;
    uint2 b = *(const uint2*)(p + 8);
    float2 f;
    f = __half22float2(*(__half2*)&a.x); w[0] = f.x;  w[1] = f.y;
    f = __half22float2(*(__half2*)&a.y); w[2] = f.x;  w[3] = f.y;
    f = __half22float2(*(__half2*)&a.z); w[4] = f.x;  w[5] = f.y;
    f = __half22float2(*(__half2*)&a.w); w[6] = f.x;  w[7] = f.y;
    f = __half22float2(*(__half2*)&b.x); w[8] = f.x;  w[9] = f.y;
    f = __half22float2(*(__half2*)&b.y); w[10] = f.x; w[11] = f.y;
}

__global__ void __launch_bounds__(NTH, 2) __cluster_dims__(2, 1, 1)
fused_kernel(const float* __restrict__ x,
             const float* __restrict__ w1, const float* __restrict__ b1,
             const float* __restrict__ w3, const float* __restrict__ b3,
             const float* __restrict__ gnw, const float* __restrict__ gnb,
             float* __restrict__ out)
{
    extern __shared__ char smraw[];
    SmC& s = *reinterpret_cast<SmC*>(smraw);
    const int tid = threadIdx.x;
    uint32_t rank;
    asm("mov.u32 %0, %%cluster_ctarank;" : "=r"(rank));
    const uint32_t prank = 1u - rank;
    const long long g = blockIdx.x >> 1;
    const int rbase = (int)rank * 32;
    const float* src = x + g * 32768;
    float* dst = out + g * 32768;
    const float4* src4 = reinterpret_cast<const float4*>(src);

    // ---- phase A: borders + params + interior load (fp16 STS) + halo row ----
    {
        const __half hz = __float2half(0.f);
        int outer = (rank == 0) ? 0 : 33;
        for (int t = tid; t < 8 * 408; t += NTH) {
            int c = t / 408;
            int u = t % 408;
            if (u < 72) {
                s.tile[c][outer][u] = hz;
            } else {
                int u2 = u - 72;
                int r = u2 >> 3;
                int row = (rank == 0) ? (r + 1) : r;
                int m = u2 & 7;
                int col = (m < 2) ? m : (64 + m);
                s.tile[c][row][col] = hz;
            }
        }
    }
    if (tid < 64) s.w1s[tid] = w1[tid] * 0.015625f;   // fold 1/64
    if (tid >= 64 && tid < 72) {
        int c = tid - 64;
        s.b1s[c] = b1[c]; s.b3s[c] = b3[c];
        s.gnws[c] = gnw[c]; s.gnbs[c] = gnb[c];
    }
    for (int t = tid; t < 576; t += NTH) s.w3s[t] = w3[t];

    {
        int i = (tid >> 4) & 31;
        int j4 = (tid & 15) << 2;
        #pragma unroll
        for (int c = 0; c < 8; c++) {
            float4 v = src4[c * 1024 + (rbase + i) * 16 + (j4 >> 2)];
            __half2* p = (__half2*)&s.tile[c][i + 1][j4 + 2];
            p[0] = __floats2half2_rn(v.x, v.y);
            p[1] = __floats2half2_rn(v.z, v.w);
        }
    }
    if (tid < 128) {
        int c = tid >> 4;
        int j4 = (tid & 15) << 2;
        int grow = (rank == 0) ? 32 : 31;
        int prow = (rank == 0) ? 33 : 0;
        float4 v = src4[c * 1024 + grow * 16 + (j4 >> 2)];
        __half2* p = (__half2*)&s.tile[c][prow][j4 + 2];
        p[0] = __floats2half2_rn(v.x, v.y);
        p[1] = __floats2half2_rn(v.z, v.w);
    }
    __syncthreads();

    // ---- phase B: rowsums (HADD2) + colsum partials (half2) + edges + corners ----
    {
        int t = tid;
        if (t < 256) {
            int c = t >> 5, i = t & 31;
            const uint4* rp = reinterpret_cast<const uint4*>(&s.tile[c][i + 1][0]);
            __half2 a0 = __float2half2_rn(0.f), a1 = a0, a2 = a0, a3 = a0;
            #pragma unroll
            for (int q = 0; q < 9; q++) {
                uint4 u = rp[q];
                a0 = __hadd2(a0, *(__half2*)&u.x);
                a1 = __hadd2(a1, *(__half2*)&u.y);
                a2 = __hadd2(a2, *(__half2*)&u.z);
                a3 = __hadd2(a3, *(__half2*)&u.w);
            }
            __half2 hs = __hadd2(__hadd2(a0, a1), __hadd2(a2, a3));
            float2 f = __half22float2(hs);
            float rsum = f.x + f.y;
            s.rowsum[c][i] = rsum;
            int edgei = (rank == 0) ? 0 : 31;
            if (i == edgei) {
                s.exedge[rank][c] = rsum;
                st_peer(&s.exedge[rank][c], prank, rsum);
            }
        } else {
            int u = t - 256;
            int c = u >> 5, jp = u & 31;     // columns 2jp, 2jp+1
            const __half2* cp = (const __half2*)&s.tile[c][1][2 + 2 * jp];
            __half2 a0 = __float2half2_rn(0.f), a1 = a0;
            #pragma unroll
            for (int r = 0; r < 32; r += 2) {
                a0 = __hadd2(a0, cp[r * (PWH / 2)]);
                a1 = __hadd2(a1, cp[(r + 1) * (PWH / 2)]);
            }
            float2 f = __half22float2(__hadd2(a0, a1));
            *(float2*)&s.excol[rank][c][2 * jp] = f;
            st_peer64(&s.excol[rank][c][2 * jp], prank, pk2(f.x, f.y));
        }
    }
    if (tid < 8) {
        int c = tid;
        float a, b;
        if (rank == 0) { a = __half2float(s.tile[c][1][2]);  b = __half2float(s.tile[c][1][65]); }
        else           { a = __half2float(s.tile[c][32][2]); b = __half2float(s.tile[c][32][65]); }
        s.excor[rank][c][0] = a;
        s.excor[rank][c][1] = b;
        st_peer(&s.excor[rank][c][0], prank, a);
        st_peer(&s.excor[rank][c][1], prank, b);
    }
    CLUSTER_SYNC();

    // ---- phase C (single pass): sh + sw (2 cols per unit) ----
    {
        int t = tid;
        if (t < 256) {
            int o = t >> 5, i = t & 31;
            float acc = s.b1s[o];
            #pragma unroll
            for (int c = 0; c < 8; c++) acc += s.w1s[o * 8 + c] * s.rowsum[c][i];
            s.sh[o][i] = sigf(acc);
        } else {
            int u = t - 256;
            int o = u >> 5;
            int v = u & 31;
            int j = 2 * v;
            int j2 = j + 1;
            float acc = s.b1s[o], acc2 = s.b1s[o];
            #pragma unroll
            for (int c = 0; c < 8; c++) {
                float cma = s.excol[0][c][j]  + s.excol[1][c][j];
                float cmb = s.excol[0][c][j2] + s.excol[1][c][j2];
                if (o == 0) { s.colm[c][j] = cma; s.colm[c][j2] = cmb; }
                float wv = s.w1s[o * 8 + c];
                acc  += wv * cma;
                acc2 += wv * cmb;
            }
            s.sw[o][j]  = sigf(acc);
            s.sw[o][j2] = sigf(acc2);
        }
    }
    __syncthreads();

    // ---- phase D: gated stats (16 warps) + warp0: T via shfl + S2l ----
    {
        int w = tid >> 5;
        int c = w >> 1;
        int half = w & 1;
        int lane = tid & 31;
        float2 swp = *(const float2*)&s.sw[c][2 * lane];
        float s0 = 0.f, s1 = 0.f, q0 = 0.f, q1 = 0.f;
        int ibase = half * 16;
        #pragma unroll 4
        for (int r = 0; r < 16; r++) {
            int i = ibase + r;
            float shi = s.sh[c][i];
            __half2 h = *(const __half2*)&s.tile[c][i + 1][2 + 2 * lane];
            float2 gf = __half22float2(h);
            float v0 = gf.x * (shi * swp.x);
            float v1 = gf.y * (shi * swp.y);
            s0 += v0; s1 += v1;
            q0 += v0 * v0; q1 += v1 * v1;
        }
        float sum = s0 + s1, sq = q0 + q1;
        #pragma unroll
        for (int off = 16; off; off >>= 1) {
            sum += __shfl_xor_sync(0xffffffffu, sum, off);
            sq  += __shfl_xor_sync(0xffffffffu, sq,  off);
        }
        if (lane == 0) {
            s.exsg[rank][c][half] = sum;  s.exsg2[rank][c][half] = sq;
            st_peer(&s.exsg[rank][c][half],  prank, sum);
            st_peer(&s.exsg2[rank][c][half], prank, sq);
        }
    }
    if (tid < 32) {
        int lane = tid;
        int c = lane & 7;
        float Tc = 0.f;
        if (lane < 8) {
            float a0 = 0.f, a1 = 0.f, a2 = 0.f, a3 = 0.f;
            int base = (c * 4) & 63;    // bank rotation
            #pragma unroll
            for (int j = 0; j < 64; j += 4) {
                int jj = (base + j) & 63;
                a0 += s.colm[c][jj];     a1 += s.colm[c][jj + 1];
                a2 += s.colm[c][jj + 2]; a3 += s.colm[c][jj + 3];
            }
            Tc = (a0 + a1) + (a2 + a3);
        }
        float acc = 0.f;
        #pragma unroll
        for (int ci = 0; ci < 8; ci++) {
            float T = __shfl_sync(0xffffffffu, Tc, ci);
            if (lane < 8) {
                float r0  = s.exedge[0][ci], r63 = s.exedge[1][ci];
                float c0  = s.colm[ci][0],   c63 = s.colm[ci][63];
                float g00 = s.excor[0][ci][0], g0e = s.excor[0][ci][1];
                float ge0 = s.excor[1][ci][0], gee = s.excor[1][ci][1];
                float Sv[9];
                Sv[0] = T - r63 - c63 + gee;
                Sv[1] = T - r63;
                Sv[2] = T - r63 - c0 + ge0;
                Sv[3] = T - c63;
                Sv[4] = T;
                Sv[5] = T - c0;
                Sv[6] = T - r0 - c63 + g0e;
                Sv[7] = T - r0;
                Sv[8] = T - r0 - c0 + g00;
                const float* wp = &s.w3s[c * 72 + ci * 9];
                #pragma unroll
                for (int k = 0; k < 9; k++) acc += wp[k] * Sv[k];
            }
        }
        if (lane < 8)
            s.S2l[c] = acc * (1.0f / 4096.0f) + s.b3s[c];
    }
    CLUSTER_SYNC();

    // ---- phase E: redundant softmaxes (80 threads) -> Weff / Aarr / Kpart ----
    if (tid < 80) {
        float mx1 = -1e30f, mx2 = -1e30f;
        #pragma unroll
        for (int k = 0; k < 8; k++) {
            mx1 = fmaxf(mx1, s.gnbs[k]);
            mx2 = fmaxf(mx2, s.S2l[k]);
        }
        float e1[8], e2[8];
        float d1 = 0.f, d2 = 0.f;
        #pragma unroll
        for (int k = 0; k < 8; k++) {
            e1[k] = __expf(s.gnbs[k] - mx1); d1 += e1[k];
            e2[k] = __expf(s.S2l[k] - mx2);  d2 += e2[k];
        }
        if (tid < 72) {
            int ci = tid / 9, tap = tid % 9;
            float acc = 0.f;
            #pragma unroll
            for (int o = 0; o < 8; o++) acc += e1[o] * s.w3s[o * 72 + ci * 9 + tap];
            s.Weff[tid] = acc / d1;
        } else {
            int c = tid - 72;
            float m = (s.exsg[0][c][0] + s.exsg[0][c][1]
                     + s.exsg[1][c][0] + s.exsg[1][c][1]) * (1.0f / 4096.0f);
            float q = (s.exsg2[0][c][0] + s.exsg2[0][c][1]
                     + s.exsg2[1][c][0] + s.exsg2[1][c][1]) * (1.0f / 4096.0f);
            float rsg = rsqrtf(q - m * m + 1e-5f);
            float x21 = e2[c] / d2;
            float x11 = e1[c] / d1;
            float gr = s.gnws[c] * rsg;
            s.Aarr[c]  = x21 * gr;
            s.Kpart[c] = x21 * (s.gnbs[c] - gr * m) + x11 * s.b3s[c];
        }
    }
    __syncthreads();

    // ---- F1: conv + gated-norm, 2 rows x 8 cols/thread, 4-way ci split ----
    {
        int cig = tid >> 7;              // ci group 0..3 -> ci {2cig, 2cig+1}
        int unit = tid & 127;
        int ip = unit >> 3;              // row pair 0..15
        int j0 = (unit & 7) << 3;        // cols j0..j0+7
        int i0 = ip << 1;                // output rows i0, i0+1
        float init = 0.f;
        if (cig == 0) {
            init = ((s.Kpart[0] + s.Kpart[1]) + (s.Kpart[2] + s.Kpart[3]))
                 + ((s.Kpart[4] + s.Kpart[5]) + (s.Kpart[6] + s.Kpart[7]));
        }
        float acc0[8], acc1[8];
        #pragma unroll
        for (int p = 0; p < 8; p++) { acc0[p] = init; acc1[p] = init; }

        #pragma unroll
        for (int cq = 0; cq < 2; cq++) {
            int ci = (cig << 1) + cq;
            const float* wc = &s.Weff[ci * 9];
            float c0w = wc[0], c1w = wc[1], c2w = wc[2];
            float c3w = wc[3], c4w = wc[4], c5w = wc[5];
            float c6w = wc[6], c7w = wc[7], c8w = wc[8];
            float aci = s.Aarr[ci];
            float coef0 = aci * s.sh[ci][i0];
            float coef1 = aci * s.sh[ci][i0 + 1];
            float4 swa = *(const float4*)&s.sw[ci][j0];
            float4 swb = *(const float4*)&s.sw[ci][j0 + 4];
            float swp[8] = {swa.x, swa.y, swa.z, swa.w, swb.x, swb.y, swb.z, swb.w};
            float w[12];
            // row i0 (padded): top taps for out0
            ld12(&s.tile[ci][i0][j0], w);
            #pragma unroll
            for (int p = 0; p < 8; p++)
                acc0[p] += c0w * w[p + 1] + c1w * w[p + 2] + c2w * w[p + 3];
            // row i0+1: mid taps for out0 (+ gate0), top taps for out1
            ld12(&s.tile[ci][i0 + 1][j0], w);
            #pragma unroll
            for (int p = 0; p < 8; p++) {
                acc0[p] += c3w * w[p + 1] + c4w * w[p + 2] + c5w * w[p + 3]
                         + coef0 * swp[p] * w[p + 2];
                acc1[p] += c0w * w[p + 1] + c1w * w[p + 2] + c2w * w[p + 3];
            }
            // row i0+2: bottom taps for out0, mid taps for out1 (+ gate1)
            ld12(&s.tile[ci][i0 + 2][j0], w);
            #pragma unroll
            for (int p = 0; p < 8; p++) {
                acc0[p] += c6w * w[p + 1] + c7w * w[p + 2] + c8w * w[p + 3];
                acc1[p] += c3w * w[p + 1] + c4w * w[p + 2] + c5w * w[p + 3]
                         + coef1 * swp[p] * w[p + 2];
            }
            // row i0+3: bottom taps for out1
            ld12(&s.tile[ci][i0 + 3][j0], w);
            #pragma unroll
            for (int p = 0; p < 8; p++)
                acc1[p] += c6w * w[p + 1] + c7w * w[p + 2] + c8w * w[p + 3];
        }
        *(float4*)&s.accp[cig][i0][j0]     = make_float4(acc0[0], acc0[1], acc0[2], acc0[3]);
        *(float4*)&s.accp[cig][i0][j0 + 4] = make_float4(acc0[4], acc0[5], acc0[6], acc0[7]);
        *(float4*)&s.accp[cig][i0 + 1][j0]     = make_float4(acc1[0], acc1[1], acc1[2], acc1[3]);
        *(float4*)&s.accp[cig][i0 + 1][j0 + 4] = make_float4(acc1[4], acc1[5], acc1[6], acc1[7]);
    }
    __syncthreads();

    // ---- F2: wt = sigmoid(sum of 4 partials); out = gx(fp16 tile) * wt ----
    // NOTE: init was added to BOTH rows of cig 0 only, so the 4-way sum carries it once.
    {
        int i = (tid >> 4) & 31;
        int j4 = (tid & 15) << 2;
        float4 p0 = *(const float4*)&s.accp[0][i][j4];
        float4 p1 = *(const float4*)&s.accp[1][i][j4];
        float4 p2 = *(const float4*)&s.accp[2][i][j4];
        float4 p3 = *(const float4*)&s.accp[3][i][j4];
        float4 wv = make_float4(
            sigf((p0.x + p1.x) + (p2.x + p3.x)),
            sigf((p0.y + p1.y) + (p2.y + p3.y)),
            sigf((p0.z + p1.z) + (p2.z + p3.z)),
            sigf((p0.w + p1.w) + (p2.w + p3.w)));
        #pragma unroll
        for (int c = 0; c < 8; c++) {
            __half2 ha = *(const __half2*)&s.tile[c][i + 1][j4 + 2];
            __half2 hb = *(const __half2*)&s.tile[c][i + 1][j4 + 4];
            float2 fa = __half22float2(ha);
            float2 fb = __half22float2(hb);
            float4 o4 = make_float4(fa.x * wv.x, fa.y * wv.y, fb.x * wv.z, fb.y * wv.w);
            *reinterpret_cast<float4*>(&dst[c * 4096 + (rbase + i) * 64 + j4]) = o4;
        }
    }
}

extern "C" void kernel_launch(void* const* d_in, const int* in_sizes, int n_in,
                              void* d_out, int out_size) {
    (void)in_sizes; (void)n_in; (void)out_size;
    const float* x   = (const float*)d_in[0];
    const float* w1  = (const float*)d_in[1];
    const float* b1  = (const float*)d_in[2];
    const float* w3  = (const float*)d_in[3];
    const float* b3  = (const float*)d_in[4];
    const float* gnw = (const float*)d_in[5];
    const float* gnb = (const float*)d_in[6];
    float* out = (float*)d_out;

    size_t smem = sizeof(SmC);
    cudaFuncSetAttribute(fused_kernel, cudaFuncAttributeMaxDynamicSharedMemorySize, (int)smem);
    fused_kernel<<<2048, NTH, smem>>>(x, w1, b1, w3, b3, gnw, gnb, out);
}

// round 16
// speedup vs baseline: 1.1970x; 1.0280x over previous
#include <cuda_runtime.h>
#include <cuda_fp16.h>
#include <cstdint>
#include <math.h>

#define PWH 72
#define NTH 512

struct SmC {
    __half tile[8][34][PWH];   // fp16 padded tile; interior rows 1..32, cols 2..65
    float excol[2][8][64];
    float colm[8][64];
    float exedge[2][8];
    float excor[2][8][2];
    float exsg[2][8][2];
    float exsg2[2][8][2];
    float rowsum[8][32];
    float sh[8][32];
    float sw[8][64];
    float accp[4][32][64];     // F1 partial sums (ci pairs 01/23/45/67)
    float w1s[64];             // pre-scaled by 1/64
    float w3s[576];
    float b1s[8], b3s[8], gnws[8], gnbs[8];
    float S2l[8];
    float Aarr[8], Kpart[8];
    float Weff[72];
};

__device__ __forceinline__ float sigf(float v) {
    return 1.0f / (1.0f + __expf(-v));
}

__device__ __forceinline__ uint32_t s2u(const void* p) {
    uint32_t a;
    asm("{ .reg .u64 t; cvta.to.shared.u64 t, %1; cvt.u32.u64 %0, t; }" : "=r"(a) : "l"(p));
    return a;
}
__device__ __forceinline__ void st_peer(const void* laddr, uint32_t prank, float v) {
    uint32_t la = s2u(laddr);
    uint32_t ra;
    asm volatile("mapa.shared::cluster.u32 %0, %1, %2;" : "=r"(ra) : "r"(la), "r"(prank));
    asm volatile("st.shared::cluster.f32 [%0], %1;" :: "r"(ra), "f"(v) : "memory");
}
__device__ __forceinline__ void st_peer64(const void* laddr, uint32_t prank, unsigned long long v) {
    uint32_t la = s2u(laddr);
    uint32_t ra;
    asm volatile("mapa.shared::cluster.u32 %0, %1, %2;" : "=r"(ra) : "r"(la), "r"(prank));
    asm volatile("st.shared::cluster.b64 [%0], %1;" :: "r"(ra), "l"(v) : "memory");
}
__device__ __forceinline__ unsigned long long pk2(float a, float b) {
    unsigned long long r;
    asm("mov.b64 %0, {%1, %2};" : "=l"(r) : "f"(a), "f"(b));
    return r;
}

#define CLUSTER_SYNC() do { \
    asm volatile("barrier.cluster.arrive.aligned;" ::: "memory"); \
    asm volatile("barrier.cluster.wait.aligned;" ::: "memory"); \
} while (0)

// load 12 consecutive padded halfs (16B-aligned) -> 12 floats
__device__ __forceinline__ void ld12(const __half* p, float* w) {
    uint4 a = *(const uint4*)p;
    uint2 b = *(const uint2*)(p + 8);
    float2 f;
    f = __half22float2(*(__half2*)&a.x); w[0] = f.x;  w[1] = f.y;
    f = __half22float2(*(__half2*)&a.y); w[2] = f.x;  w[3] = f.y;
    f = __half22float2(*(__half2*)&a.z); w[4] = f.x;  w[5] = f.y;
    f = __half22float2(*(__half2*)&a.w); w[6] = f.x;  w[7] = f.y;
    f = __half22float2(*(__half2*)&b.x); w[8] = f.x;  w[9] = f.y;
    f = __half22float2(*(__half2*)&b.y); w[10] = f.x; w[11] = f.y;
}

__global__ void __launch_bounds__(NTH, 2) __cluster_dims__(2, 1, 1)
fused_kernel(const float* __restrict__ x,
             const float* __restrict__ w1, const float* __restrict__ b1,
             const float* __restrict__ w3, const float* __restrict__ b3,
             const float* __restrict__ gnw, const float* __restrict__ gnb,
             float* __restrict__ out)
{
    extern __shared__ char smraw[];
    SmC& s = *reinterpret_cast<SmC*>(smraw);
    const int tid = threadIdx.x;
    uint32_t rank;
    asm("mov.u32 %0, %%cluster_ctarank;" : "=r"(rank));
    const uint32_t prank = 1u - rank;
    const long long g = blockIdx.x >> 1;
    const int rbase = (int)rank * 32;
    const float* src = x + g * 32768;
    float* dst = out + g * 32768;
    const float4* src4 = reinterpret_cast<const float4*>(src);

    // ---- phase A: issue tile loads FIRST, overlap border zero + params ----
    const int li = (tid >> 4) & 31;
    const int lj4 = (tid & 15) << 2;
    const float4* lbase = src4 + (rbase + li) * 16 + (lj4 >> 2);

    float4 va0 = lbase[0 * 1024];
    float4 va1 = lbase[1 * 1024];
    float4 va2 = lbase[2 * 1024];
    float4 va3 = lbase[3 * 1024];
    float4 vhalo;
    const int hc = tid >> 4;
    const int hj4 = (tid & 15) << 2;
    if (tid < 128) {
        int grow = (rank == 0) ? 32 : 31;
        vhalo = src4[hc * 1024 + grow * 16 + (hj4 >> 2)];
    }

    // border zeroing + params while loads are in flight
    {
        const __half hz = __float2half(0.f);
        int outer = (rank == 0) ? 0 : 33;
        for (int t = tid; t < 8 * 408; t += NTH) {
            int c = t / 408;
            int u = t % 408;
            if (u < 72) {
                s.tile[c][outer][u] = hz;
            } else {
                int u2 = u - 72;
                int r = u2 >> 3;
                int row = (rank == 0) ? (r + 1) : r;
                int m = u2 & 7;
                int col = (m < 2) ? m : (64 + m);
                s.tile[c][row][col] = hz;
            }
        }
    }
    if (tid < 64) s.w1s[tid] = w1[tid] * 0.015625f;   // fold 1/64
    if (tid >= 64 && tid < 72) {
        int c = tid - 64;
        s.b1s[c] = b1[c]; s.b3s[c] = b3[c];
        s.gnws[c] = gnw[c]; s.gnbs[c] = gnb[c];
    }
    for (int t = tid; t < 576; t += NTH) s.w3s[t] = w3[t];

    // store batch 1, issue batch 2, store batch 2
    {
        float4 vb0 = lbase[4 * 1024];
        float4 vb1 = lbase[5 * 1024];
        float4 vb2 = lbase[6 * 1024];
        float4 vb3 = lbase[7 * 1024];
        __half2* p;
        p = (__half2*)&s.tile[0][li + 1][lj4 + 2];
        p[0] = __floats2half2_rn(va0.x, va0.y); p[1] = __floats2half2_rn(va0.z, va0.w);
        p = (__half2*)&s.tile[1][li + 1][lj4 + 2];
        p[0] = __floats2half2_rn(va1.x, va1.y); p[1] = __floats2half2_rn(va1.z, va1.w);
        p = (__half2*)&s.tile[2][li + 1][lj4 + 2];
        p[0] = __floats2half2_rn(va2.x, va2.y); p[1] = __floats2half2_rn(va2.z, va2.w);
        p = (__half2*)&s.tile[3][li + 1][lj4 + 2];
        p[0] = __floats2half2_rn(va3.x, va3.y); p[1] = __floats2half2_rn(va3.z, va3.w);
        p = (__half2*)&s.tile[4][li + 1][lj4 + 2];
        p[0] = __floats2half2_rn(vb0.x, vb0.y); p[1] = __floats2half2_rn(vb0.z, vb0.w);
        p = (__half2*)&s.tile[5][li + 1][lj4 + 2];
        p[0] = __floats2half2_rn(vb1.x, vb1.y); p[1] = __floats2half2_rn(vb1.z, vb1.w);
        p = (__half2*)&s.tile[6][li + 1][lj4 + 2];
        p[0] = __floats2half2_rn(vb2.x, vb2.y); p[1] = __floats2half2_rn(vb2.z, vb2.w);
        p = (__half2*)&s.tile[7][li + 1][lj4 + 2];
        p[0] = __floats2half2_rn(vb3.x, vb3.y); p[1] = __floats2half2_rn(vb3.z, vb3.w);
    }
    if (tid < 128) {
        int prow = (rank == 0) ? 33 : 0;
        __half2* p = (__half2*)&s.tile[hc][prow][hj4 + 2];
        p[0] = __floats2half2_rn(vhalo.x, vhalo.y);
        p[1] = __floats2half2_rn(vhalo.z, vhalo.w);
    }
    __syncthreads();

    // ---- phase B: rowsums (HADD2) + colsum partials (half2) + edges + corners ----
    {
        int t = tid;
        if (t < 256) {
            int c = t >> 5, i = t & 31;
            const uint4* rp = reinterpret_cast<const uint4*>(&s.tile[c][i + 1][0]);
            __half2 a0 = __float2half2_rn(0.f), a1 = a0, a2 = a0, a3 = a0;
            #pragma unroll
            for (int q = 0; q < 9; q++) {
                uint4 u = rp[q];
                a0 = __hadd2(a0, *(__half2*)&u.x);
                a1 = __hadd2(a1, *(__half2*)&u.y);
                a2 = __hadd2(a2, *(__half2*)&u.z);
                a3 = __hadd2(a3, *(__half2*)&u.w);
            }
            __half2 hs = __hadd2(__hadd2(a0, a1), __hadd2(a2, a3));
            float2 f = __half22float2(hs);
            float rsum = f.x + f.y;
            s.rowsum[c][i] = rsum;
            int edgei = (rank == 0) ? 0 : 31;
            if (i == edgei) {
                s.exedge[rank][c] = rsum;
                st_peer(&s.exedge[rank][c], prank, rsum);
            }
        } else {
            int u = t - 256;
            int c = u >> 5, jp = u & 31;     // columns 2jp, 2jp+1
            const __half2* cp = (const __half2*)&s.tile[c][1][2 + 2 * jp];
            __half2 a0 = __float2half2_rn(0.f), a1 = a0;
            #pragma unroll
            for (int r = 0; r < 32; r += 2) {
                a0 = __hadd2(a0, cp[r * (PWH / 2)]);
                a1 = __hadd2(a1, cp[(r + 1) * (PWH / 2)]);
            }
            float2 f = __half22float2(__hadd2(a0, a1));
            *(float2*)&s.excol[rank][c][2 * jp] = f;
            st_peer64(&s.excol[rank][c][2 * jp], prank, pk2(f.x, f.y));
        }
    }
    if (tid < 8) {
        int c = tid;
        float a, b;
        if (rank == 0) { a = __half2float(s.tile[c][1][2]);  b = __half2float(s.tile[c][1][65]); }
        else           { a = __half2float(s.tile[c][32][2]); b = __half2float(s.tile[c][32][65]); }
        s.excor[rank][c][0] = a;
        s.excor[rank][c][1] = b;
        st_peer(&s.excor[rank][c][0], prank, a);
        st_peer(&s.excor[rank][c][1], prank, b);
    }
    CLUSTER_SYNC();

    // ---- phase C (single pass): sh + sw (2 cols per unit) ----
    {
        int t = tid;
        if (t < 256) {
            int o = t >> 5, i = t & 31;
            float acc = s.b1s[o];
            #pragma unroll
            for (int c = 0; c < 8; c++) acc += s.w1s[o * 8 + c] * s.rowsum[c][i];
            s.sh[o][i] = sigf(acc);
        } else {
            int u = t - 256;
            int o = u >> 5;
            int v = u & 31;
            int j = 2 * v;
            int j2 = j + 1;
            float acc = s.b1s[o], acc2 = s.b1s[o];
            #pragma unroll
            for (int c = 0; c < 8; c++) {
                float cma = s.excol[0][c][j]  + s.excol[1][c][j];
                float cmb = s.excol[0][c][j2] + s.excol[1][c][j2];
                if (o == 0) { s.colm[c][j] = cma; s.colm[c][j2] = cmb; }
                float wv = s.w1s[o * 8 + c];
                acc  += wv * cma;
                acc2 += wv * cmb;
            }
            s.sw[o][j]  = sigf(acc);
            s.sw[o][j2] = sigf(acc2);
        }
    }
    __syncthreads();

    // ---- phase D: gated stats (16 warps) + warp0: T via shfl + S2l ----
    {
        int w = tid >> 5;
        int c = w >> 1;
        int half = w & 1;
        int lane = tid & 31;
        float2 swp = *(const float2*)&s.sw[c][2 * lane];
        float s0 = 0.f, s1 = 0.f, q0 = 0.f, q1 = 0.f;
        int ibase = half * 16;
        #pragma unroll 4
        for (int r = 0; r < 16; r++) {
            int i = ibase + r;
            float shi = s.sh[c][i];
            __half2 h = *(const __half2*)&s.tile[c][i + 1][2 + 2 * lane];
            float2 gf = __half22float2(h);
            float v0 = gf.x * (shi * swp.x);
            float v1 = gf.y * (shi * swp.y);
            s0 += v0; s1 += v1;
            q0 += v0 * v0; q1 += v1 * v1;
        }
        float sum = s0 + s1, sq = q0 + q1;
        #pragma unroll
        for (int off = 16; off; off >>= 1) {
            sum += __shfl_xor_sync(0xffffffffu, sum, off);
            sq  += __shfl_xor_sync(0xffffffffu, sq,  off);
        }
        if (lane == 0) {
            s.exsg[rank][c][half] = sum;  s.exsg2[rank][c][half] = sq;
            st_peer(&s.exsg[rank][c][half],  prank, sum);
            st_peer(&s.exsg2[rank][c][half], prank, sq);
        }
    }
    if (tid < 32) {
        int lane = tid;
        int c = lane & 7;
        float Tc = 0.f;
        if (lane < 8) {
            float a0 = 0.f, a1 = 0.f, a2 = 0.f, a3 = 0.f;
            int base = (c * 4) & 63;    // bank rotation
            #pragma unroll
            for (int j = 0; j < 64; j += 4) {
                int jj = (base + j) & 63;
                a0 += s.colm[c][jj];     a1 += s.colm[c][jj + 1];
                a2 += s.colm[c][jj + 2]; a3 += s.colm[c][jj + 3];
            }
            Tc = (a0 + a1) + (a2 + a3);
        }
        float acc = 0.f;
        #pragma unroll
        for (int ci = 0; ci < 8; ci++) {
            float T = __shfl_sync(0xffffffffu, Tc, ci);
            if (lane < 8) {
                float r0  = s.exedge[0][ci], r63 = s.exedge[1][ci];
                float c0  = s.colm[ci][0],   c63 = s.colm[ci][63];
                float g00 = s.excor[0][ci][0], g0e = s.excor[0][ci][1];
                float ge0 = s.excor[1][ci][0], gee = s.excor[1][ci][1];
                float Sv[9];
                Sv[0] = T - r63 - c63 + gee;
                Sv[1] = T - r63;
                Sv[2] = T - r63 - c0 + ge0;
                Sv[3] = T - c63;
                Sv[4] = T;
                Sv[5] = T - c0;
                Sv[6] = T - r0 - c63 + g0e;
                Sv[7] = T - r0;
                Sv[8] = T - r0 - c0 + g00;
                const float* wp = &s.w3s[c * 72 + ci * 9];
                #pragma unroll
                for (int k = 0; k < 9; k++) acc += wp[k] * Sv[k];
            }
        }
        if (lane < 8)
            s.S2l[c] = acc * (1.0f / 4096.0f) + s.b3s[c];
    }
    CLUSTER_SYNC();

    // ---- phase E: redundant softmaxes (80 threads) -> Weff / Aarr / Kpart ----
    if (tid < 80) {
        float mx1 = -1e30f, mx2 = -1e30f;
        #pragma unroll
        for (int k = 0; k < 8; k++) {
            mx1 = fmaxf(mx1, s.gnbs[k]);
            mx2 = fmaxf(mx2, s.S2l[k]);
        }
        float e1[8], e2[8];
        float d1 = 0.f, d2 = 0.f;
        #pragma unroll
        for (int k = 0; k < 8; k++) {
            e1[k] = __expf(s.gnbs[k] - mx1); d1 += e1[k];
            e2[k] = __expf(s.S2l[k] - mx2);  d2 += e2[k];
        }
        if (tid < 72) {
            int ci = tid / 9, tap = tid % 9;
            float acc = 0.f;
            #pragma unroll
            for (int o = 0; o < 8; o++) acc += e1[o] * s.w3s[o * 72 + ci * 9 + tap];
            s.Weff[tid] = acc / d1;
        } else {
            int c = tid - 72;
            float m = (s.exsg[0][c][0] + s.exsg[0][c][1]
                     + s.exsg[1][c][0] + s.exsg[1][c][1]) * (1.0f / 4096.0f);
            float q = (s.exsg2[0][c][0] + s.exsg2[0][c][1]
                     + s.exsg2[1][c][0] + s.exsg2[1][c][1]) * (1.0f / 4096.0f);
            float rsg = rsqrtf(q - m * m + 1e-5f);
            float x21 = e2[c] / d2;
            float x11 = e1[c] / d1;
            float gr = s.gnws[c] * rsg;
            s.Aarr[c]  = x21 * gr;
            s.Kpart[c] = x21 * (s.gnbs[c] - gr * m) + x11 * s.b3s[c];
        }
    }
    __syncthreads();

    // ---- F1: conv + gated-norm, 2 rows x 8 cols/thread, 4-way ci split ----
    {
        int cig = tid >> 7;              // ci group 0..3 -> ci {2cig, 2cig+1}
        int unit = tid & 127;
        int ip = unit >> 3;              // row pair 0..15
        int j0 = (unit & 7) << 3;        // cols j0..j0+7
        int i0 = ip << 1;                // output rows i0, i0+1
        float init = 0.f;
        if (cig == 0) {
            init = ((s.Kpart[0] + s.Kpart[1]) + (s.Kpart[2] + s.Kpart[3]))
                 + ((s.Kpart[4] + s.Kpart[5]) + (s.Kpart[6] + s.Kpart[7]));
        }
        float acc0[8], acc1[8];
        #pragma unroll
        for (int p = 0; p < 8; p++) { acc0[p] = init; acc1[p] = init; }

        #pragma unroll
        for (int cq = 0; cq < 2; cq++) {
            int ci = (cig << 1) + cq;
            const float* wc = &s.Weff[ci * 9];
            float c0w = wc[0], c1w = wc[1], c2w = wc[2];
            float c3w = wc[3], c4w = wc[4], c5w = wc[5];
            float c6w = wc[6], c7w = wc[7], c8w = wc[8];
            float aci = s.Aarr[ci];
            float coef0 = aci * s.sh[ci][i0];
            float coef1 = aci * s.sh[ci][i0 + 1];
            float4 swa = *(const float4*)&s.sw[ci][j0];
            float4 swb = *(const float4*)&s.sw[ci][j0 + 4];
            float swp[8] = {swa.x, swa.y, swa.z, swa.w, swb.x, swb.y, swb.z, swb.w};
            float w[12];
            ld12(&s.tile[ci][i0][j0], w);
            #pragma unroll
            for (int p = 0; p < 8; p++)
                acc0[p] += c0w * w[p + 1] + c1w * w[p + 2] + c2w * w[p + 3];
            ld12(&s.tile[ci][i0 + 1][j0], w);
            #pragma unroll
            for (int p = 0; p < 8; p++) {
                acc0[p] += c3w * w[p + 1] + c4w * w[p + 2] + c5w * w[p + 3]
                         + coef0 * swp[p] * w[p + 2];
                acc1[p] += c0w * w[p + 1] + c1w * w[p + 2] + c2w * w[p + 3];
            }
            ld12(&s.tile[ci][i0 + 2][j0], w);
            #pragma unroll
            for (int p = 0; p < 8; p++) {
                acc0[p] += c6w * w[p + 1] + c7w * w[p + 2] + c8w * w[p + 3];
                acc1[p] += c3w * w[p + 1] + c4w * w[p + 2] + c5w * w[p + 3]
                         + coef1 * swp[p] * w[p + 2];
            }
            ld12(&s.tile[ci][i0 + 3][j0], w);
            #pragma unroll
            for (int p = 0; p < 8; p++)
                acc1[p] += c6w * w[p + 1] + c7w * w[p + 2] + c8w * w[p + 3];
        }
        *(float4*)&s.accp[cig][i0][j0]     = make_float4(acc0[0], acc0[1], acc0[2], acc0[3]);
        *(float4*)&s.accp[cig][i0][j0 + 4] = make_float4(acc0[4], acc0[5], acc0[6], acc0[7]);
        *(float4*)&s.accp[cig][i0 + 1][j0]     = make_float4(acc1[0], acc1[1], acc1[2], acc1[3]);
        *(float4*)&s.accp[cig][i0 + 1][j0 + 4] = make_float4(acc1[4], acc1[5], acc1[6], acc1[7]);
    }
    __syncthreads();

    // ---- F2: wt = sigmoid(sum of 4 partials); out = gx(fp16 tile) * wt ----
    // init was added to both rows of ALL cig groups; only cig 0 carries it, others start at init too?
    // NOTE: init is nonzero only for cig==0, so the 4-way sum carries it exactly once.
    {
        int i = (tid >> 4) & 31;
        int j4 = (tid & 15) << 2;
        float4 p0 = *(const float4*)&s.accp[0][i][j4];
        float4 p1 = *(const float4*)&s.accp[1][i][j4];
        float4 p2 = *(const float4*)&s.accp[2][i][j4];
        float4 p3 = *(const float4*)&s.accp[3][i][j4];
        float4 wv = make_float4(
            sigf((p0.x + p1.x) + (p2.x + p3.x)),
            sigf((p0.y + p1.y) + (p2.y + p3.y)),
            sigf((p0.z + p1.z) + (p2.z + p3.z)),
            sigf((p0.w + p1.w) + (p2.w + p3.w)));
        #pragma unroll
        for (int c = 0; c < 8; c++) {
            __half2 ha = *(const __half2*)&s.tile[c][i + 1][j4 + 2];
            __half2 hb = *(const __half2*)&s.tile[c][i + 1][j4 + 4];
            float2 fa = __half22float2(ha);
            float2 fb = __half22float2(hb);
            float4 o4 = make_float4(fa.x * wv.x, fa.y * wv.y, fb.x * wv.z, fb.y * wv.w);
            *reinterpret_cast<float4*>(&dst[c * 4096 + (rbase + i) * 64 + j4]) = o4;
        }
    }
}

extern "C" void kernel_launch(void* const* d_in, const int* in_sizes, int n_in,
                              void* d_out, int out_size) {
    (void)in_sizes; (void)n_in; (void)out_size;
    const float* x   = (const float*)d_in[0];
    const float* w1  = (const float*)d_in[1];
    const float* b1  = (const float*)d_in[2];
    const float* w3  = (const float*)d_in[3];
    const float* b3  = (const float*)d_in[4];
    const float* gnw = (const float*)d_in[5];
    const float* gnb = (const float*)d_in[6];
    float* out = (float*)d_out;

    size_t smem = sizeof(SmC);
    cudaFuncSetAttribute(fused_kernel, cudaFuncAttributeMaxDynamicSharedMemorySize, (int)smem);
    fused_kernel<<<2048, NTH, smem>>>(x, w1, b1, w3, b3, gnw, gnb, out);
}

// round 17
// speedup vs baseline: 1.2119x; 1.0125x over previous
#include <cuda_runtime.h>
#include <cuda_fp16.h>
#include <cstdint>
#include <math.h>

#define PWH 72
#define NTH 512

struct SmC {
    __half tile[8][34][PWH];   // fp16 padded tile; interior rows 1..32, cols 2..65
    float excol[2][8][64];
    float colm[8][64];
    float exedge[2][8];
    float excor[2][8][2];
    float exsg[2][8][2];
    float exsg2[2][8][2];
    float rowsum[8][32];
    float sh[8][32];
    float sw[8][64];
    float accp[4][32][64];     // F1 partial sums (ci pairs 01/23/45/67)
    float w1s[64];             // pre-scaled by 1/64
    float w3s[576];
    float b1s[8], b3s[8], gnws[8], gnbs[8];
    float S2l[8];
    float Aarr[8], Kpart[8];
    float Weff[72];
};

// sigmoid via single-MUFU tanh.approx: sigmoid(x) = 0.5*tanh(0.5x) + 0.5
__device__ __forceinline__ float sigf(float v) {
    float t;
    asm("tanh.approx.f32 %0, %1;" : "=f"(t) : "f"(v * 0.5f));
    return fmaf(t, 0.5f, 0.5f);
}

__device__ __forceinline__ uint32_t s2u(const void* p) {
    uint32_t a;
    asm("{ .reg .u64 t; cvta.to.shared.u64 t, %1; cvt.u32.u64 %0, t; }" : "=r"(a) : "l"(p));
    return a;
}
__device__ __forceinline__ void st_peer(const void* laddr, uint32_t prank, float v) {
    uint32_t la = s2u(laddr);
    uint32_t ra;
    asm volatile("mapa.shared::cluster.u32 %0, %1, %2;" : "=r"(ra) : "r"(la), "r"(prank));
    asm volatile("st.shared::cluster.f32 [%0], %1;" :: "r"(ra), "f"(v) : "memory");
}
__device__ __forceinline__ void st_peer64(const void* laddr, uint32_t prank, unsigned long long v) {
    uint32_t la = s2u(laddr);
    uint32_t ra;
    asm volatile("mapa.shared::cluster.u32 %0, %1, %2;" : "=r"(ra) : "r"(la), "r"(prank));
    asm volatile("st.shared::cluster.b64 [%0], %1;" :: "r"(ra), "l"(v) : "memory");
}
__device__ __forceinline__ unsigned long long pk2(float a, float b) {
    unsigned long long r;
    asm("mov.b64 %0, {%1, %2};" : "=l"(r) : "f"(a), "f"(b));
    return r;
}

#define CLUSTER_SYNC() do { \
    asm volatile("barrier.cluster.arrive.aligned;" ::: "memory"); \
    asm volatile("barrier.cluster.wait.aligned;" ::: "memory"); \
} while (0)

// load 12 consecutive padded halfs (16B-aligned) -> 12 floats
__device__ __forceinline__ void ld12(const __half* p, float* w) {
    uint4 a = *(const uint4*)p;
    uint2 b = *(const uint2*)(p + 8);
    float2 f;
    f = __half22float2(*(__half2*)&a.x); w[0] = f.x;  w[1] = f.y;
    f = __half22float2(*(__half2*)&a.y); w[2] = f.x;  w[3] = f.y;
    f = __half22float2(*(__half2*)&a.z); w[4] = f.x;  w[5] = f.y;
    f = __half22float2(*(__half2*)&a.w); w[6] = f.x;  w[7] = f.y;
    f = __half22float2(*(__half2*)&b.x); w[8] = f.x;  w[9] = f.y;
    f = __half22float2(*(__half2*)&b.y); w[10] = f.x; w[11] = f.y;
}

__global__ void __launch_bounds__(NTH, 2) __cluster_dims__(2, 1, 1)
fused_kernel(const float* __restrict__ x,
             const float* __restrict__ w1, const float* __restrict__ b1,
             const float* __restrict__ w3, const float* __restrict__ b3,
             const float* __restrict__ gnw, const float* __restrict__ gnb,
             float* __restrict__ out)
{
    extern __shared__ char smraw[];
    SmC& s = *reinterpret_cast<SmC*>(smraw);
    const int tid = threadIdx.x;
    uint32_t rank;
    asm("mov.u32 %0, %%cluster_ctarank;" : "=r"(rank));
    const uint32_t prank = 1u - rank;
    const long long g = blockIdx.x >> 1;
    const int rbase = (int)rank * 32;
    const float* src = x + g * 32768;
    float* dst = out + g * 32768;
    const float4* src4 = reinterpret_cast<const float4*>(src);

    // ---- phase A: issue tile loads FIRST, overlap border zero + params ----
    const int li = (tid >> 4) & 31;
    const int lj4 = (tid & 15) << 2;
    const float4* lbase = src4 + (rbase + li) * 16 + (lj4 >> 2);

    float4 va0 = lbase[0 * 1024];
    float4 va1 = lbase[1 * 1024];
    float4 va2 = lbase[2 * 1024];
    float4 va3 = lbase[3 * 1024];
    float4 vhalo;
    const int hc = tid >> 4;
    const int hj4 = (tid & 15) << 2;
    if (tid < 128) {
        int grow = (rank == 0) ? 32 : 31;
        vhalo = src4[hc * 1024 + grow * 16 + (hj4 >> 2)];
    }

    // border zeroing + params while loads are in flight
    {
        const __half hz = __float2half(0.f);
        int outer = (rank == 0) ? 0 : 33;
        for (int t = tid; t < 8 * 408; t += NTH) {
            int c = t / 408;
            int u = t % 408;
            if (u < 72) {
                s.tile[c][outer][u] = hz;
            } else {
                int u2 = u - 72;
                int r = u2 >> 3;
                int row = (rank == 0) ? (r + 1) : r;
                int m = u2 & 7;
                int col = (m < 2) ? m : (64 + m);
                s.tile[c][row][col] = hz;
            }
        }
    }
    if (tid < 64) s.w1s[tid] = w1[tid] * 0.015625f;   // fold 1/64
    if (tid >= 64 && tid < 72) {
        int c = tid - 64;
        s.b1s[c] = b1[c]; s.b3s[c] = b3[c];
        s.gnws[c] = gnw[c]; s.gnbs[c] = gnb[c];
    }
    for (int t = tid; t < 576; t += NTH) s.w3s[t] = w3[t];

    // store batch 1, issue batch 2, store batch 2
    {
        float4 vb0 = lbase[4 * 1024];
        float4 vb1 = lbase[5 * 1024];
        float4 vb2 = lbase[6 * 1024];
        float4 vb3 = lbase[7 * 1024];
        __half2* p;
        p = (__half2*)&s.tile[0][li + 1][lj4 + 2];
        p[0] = __floats2half2_rn(va0.x, va0.y); p[1] = __floats2half2_rn(va0.z, va0.w);
        p = (__half2*)&s.tile[1][li + 1][lj4 + 2];
        p[0] = __floats2half2_rn(va1.x, va1.y); p[1] = __floats2half2_rn(va1.z, va1.w);
        p = (__half2*)&s.tile[2][li + 1][lj4 + 2];
        p[0] = __floats2half2_rn(va2.x, va2.y); p[1] = __floats2half2_rn(va2.z, va2.w);
        p = (__half2*)&s.tile[3][li + 1][lj4 + 2];
        p[0] = __floats2half2_rn(va3.x, va3.y); p[1] = __floats2half2_rn(va3.z, va3.w);
        p = (__half2*)&s.tile[4][li + 1][lj4 + 2];
        p[0] = __floats2half2_rn(vb0.x, vb0.y); p[1] = __floats2half2_rn(vb0.z, vb0.w);
        p = (__half2*)&s.tile[5][li + 1][lj4 + 2];
        p[0] = __floats2half2_rn(vb1.x, vb1.y); p[1] = __floats2half2_rn(vb1.z, vb1.w);
        p = (__half2*)&s.tile[6][li + 1][lj4 + 2];
        p[0] = __floats2half2_rn(vb2.x, vb2.y); p[1] = __floats2half2_rn(vb2.z, vb2.w);
        p = (__half2*)&s.tile[7][li + 1][lj4 + 2];
        p[0] = __floats2half2_rn(vb3.x, vb3.y); p[1] = __floats2half2_rn(vb3.z, vb3.w);
    }
    if (tid < 128) {
        int prow = (rank == 0) ? 33 : 0;
        __half2* p = (__half2*)&s.tile[hc][prow][hj4 + 2];
        p[0] = __floats2half2_rn(vhalo.x, vhalo.y);
        p[1] = __floats2half2_rn(vhalo.z, vhalo.w);
    }
    __syncthreads();

    // ---- phase B: rowsums (HADD2) + colsum partials (half2) + edges + corners ----
    {
        int t = tid;
        if (t < 256) {
            int c = t >> 5, i = t & 31;
            const uint4* rp = reinterpret_cast<const uint4*>(&s.tile[c][i + 1][0]);
            __half2 a0 = __float2half2_rn(0.f), a1 = a0, a2 = a0, a3 = a0;
            #pragma unroll
            for (int q = 0; q < 9; q++) {
                uint4 u = rp[q];
                a0 = __hadd2(a0, *(__half2*)&u.x);
                a1 = __hadd2(a1, *(__half2*)&u.y);
                a2 = __hadd2(a2, *(__half2*)&u.z);
                a3 = __hadd2(a3, *(__half2*)&u.w);
            }
            __half2 hs = __hadd2(__hadd2(a0, a1), __hadd2(a2, a3));
            float2 f = __half22float2(hs);
            float rsum = f.x + f.y;
            s.rowsum[c][i] = rsum;
            int edgei = (rank == 0) ? 0 : 31;
            if (i == edgei) {
                s.exedge[rank][c] = rsum;
                st_peer(&s.exedge[rank][c], prank, rsum);
            }
        } else {
            int u = t - 256;
            int c = u >> 5, jp = u & 31;     // columns 2jp, 2jp+1
            const __half2* cp = (const __half2*)&s.tile[c][1][2 + 2 * jp];
            __half2 a0 = __float2half2_rn(0.f), a1 = a0;
            #pragma unroll
            for (int r = 0; r < 32; r += 2) {
                a0 = __hadd2(a0, cp[r * (PWH / 2)]);
                a1 = __hadd2(a1, cp[(r + 1) * (PWH / 2)]);
            }
            float2 f = __half22float2(__hadd2(a0, a1));
            *(float2*)&s.excol[rank][c][2 * jp] = f;
            st_peer64(&s.excol[rank][c][2 * jp], prank, pk2(f.x, f.y));
        }
    }
    if (tid < 8) {
        int c = tid;
        float a, b;
        if (rank == 0) { a = __half2float(s.tile[c][1][2]);  b = __half2float(s.tile[c][1][65]); }
        else           { a = __half2float(s.tile[c][32][2]); b = __half2float(s.tile[c][32][65]); }
        s.excor[rank][c][0] = a;
        s.excor[rank][c][1] = b;
        st_peer(&s.excor[rank][c][0], prank, a);
        st_peer(&s.excor[rank][c][1], prank, b);
    }
    CLUSTER_SYNC();

    // ---- phase C (single pass): sh + sw (2 cols per unit) ----
    {
        int t = tid;
        if (t < 256) {
            int o = t >> 5, i = t & 31;
            float acc = s.b1s[o];
            #pragma unroll
            for (int c = 0; c < 8; c++) acc += s.w1s[o * 8 + c] * s.rowsum[c][i];
            s.sh[o][i] = sigf(acc);
        } else {
            int u = t - 256;
            int o = u >> 5;
            int v = u & 31;
            int j = 2 * v;
            int j2 = j + 1;
            float acc = s.b1s[o], acc2 = s.b1s[o];
            #pragma unroll
            for (int c = 0; c < 8; c++) {
                float cma = s.excol[0][c][j]  + s.excol[1][c][j];
                float cmb = s.excol[0][c][j2] + s.excol[1][c][j2];
                if (o == 0) { s.colm[c][j] = cma; s.colm[c][j2] = cmb; }
                float wv = s.w1s[o * 8 + c];
                acc  += wv * cma;
                acc2 += wv * cmb;
            }
            s.sw[o][j]  = sigf(acc);
            s.sw[o][j2] = sigf(acc2);
        }
    }
    __syncthreads();

    // ---- phase D: gated stats (16 warps) + warp0: T via shfl + S2l ----
    {
        int w = tid >> 5;
        int c = w >> 1;
        int half = w & 1;
        int lane = tid & 31;
        float2 swp = *(const float2*)&s.sw[c][2 * lane];
        float s0 = 0.f, s1 = 0.f, q0 = 0.f, q1 = 0.f;
        int ibase = half * 16;
        #pragma unroll 4
        for (int r = 0; r < 16; r++) {
            int i = ibase + r;
            float shi = s.sh[c][i];
            __half2 h = *(const __half2*)&s.tile[c][i + 1][2 + 2 * lane];
            float2 gf = __half22float2(h);
            float v0 = gf.x * (shi * swp.x);
            float v1 = gf.y * (shi * swp.y);
            s0 += v0; s1 += v1;
            q0 += v0 * v0; q1 += v1 * v1;
        }
        float sum = s0 + s1, sq = q0 + q1;
        #pragma unroll
        for (int off = 16; off; off >>= 1) {
            sum += __shfl_xor_sync(0xffffffffu, sum, off);
            sq  += __shfl_xor_sync(0xffffffffu, sq,  off);
        }
        if (lane == 0) {
            s.exsg[rank][c][half] = sum;  s.exsg2[rank][c][half] = sq;
            st_peer(&s.exsg[rank][c][half],  prank, sum);
            st_peer(&s.exsg2[rank][c][half], prank, sq);
        }
    }
    if (tid < 32) {
        int lane = tid;
        int c = lane & 7;
        float Tc = 0.f;
        if (lane < 8) {
            float a0 = 0.f, a1 = 0.f, a2 = 0.f, a3 = 0.f;
            int base = (c * 4) & 63;    // bank rotation
            #pragma unroll
            for (int j = 0; j < 64; j += 4) {
                int jj = (base + j) & 63;
                a0 += s.colm[c][jj];     a1 += s.colm[c][jj + 1];
                a2 += s.colm[c][jj + 2]; a3 += s.colm[c][jj + 3];
            }
            Tc = (a0 + a1) + (a2 + a3);
        }
        float acc = 0.f;
        #pragma unroll
        for (int ci = 0; ci < 8; ci++) {
            float T = __shfl_sync(0xffffffffu, Tc, ci);
            if (lane < 8) {
                float r0  = s.exedge[0][ci], r63 = s.exedge[1][ci];
                float c0  = s.colm[ci][0],   c63 = s.colm[ci][63];
                float g00 = s.excor[0][ci][0], g0e = s.excor[0][ci][1];
                float ge0 = s.excor[1][ci][0], gee = s.excor[1][ci][1];
                float Sv[9];
                Sv[0] = T - r63 - c63 + gee;
                Sv[1] = T - r63;
                Sv[2] = T - r63 - c0 + ge0;
                Sv[3] = T - c63;
                Sv[4] = T;
                Sv[5] = T - c0;
                Sv[6] = T - r0 - c63 + g0e;
                Sv[7] = T - r0;
                Sv[8] = T - r0 - c0 + g00;
                const float* wp = &s.w3s[c * 72 + ci * 9];
                #pragma unroll
                for (int k = 0; k < 9; k++) acc += wp[k] * Sv[k];
            }
        }
        if (lane < 8)
            s.S2l[c] = acc * (1.0f / 4096.0f) + s.b3s[c];
    }
    CLUSTER_SYNC();

    // ---- phase E: redundant softmaxes (80 threads) -> Weff / Aarr / Kpart ----
    if (tid < 80) {
        float mx1 = -1e30f, mx2 = -1e30f;
        #pragma unroll
        for (int k = 0; k < 8; k++) {
            mx1 = fmaxf(mx1, s.gnbs[k]);
            mx2 = fmaxf(mx2, s.S2l[k]);
        }
        float e1[8], e2[8];
        float d1 = 0.f, d2 = 0.f;
        #pragma unroll
        for (int k = 0; k < 8; k++) {
            e1[k] = __expf(s.gnbs[k] - mx1); d1 += e1[k];
            e2[k] = __expf(s.S2l[k] - mx2);  d2 += e2[k];
        }
        if (tid < 72) {
            int ci = tid / 9, tap = tid % 9;
            float acc = 0.f;
            #pragma unroll
            for (int o = 0; o < 8; o++) acc += e1[o] * s.w3s[o * 72 + ci * 9 + tap];
            s.Weff[tid] = acc / d1;
        } else {
            int c = tid - 72;
            float m = (s.exsg[0][c][0] + s.exsg[0][c][1]
                     + s.exsg[1][c][0] + s.exsg[1][c][1]) * (1.0f / 4096.0f);
            float q = (s.exsg2[0][c][0] + s.exsg2[0][c][1]
                     + s.exsg2[1][c][0] + s.exsg2[1][c][1]) * (1.0f / 4096.0f);
            float rsg = rsqrtf(q - m * m + 1e-5f);
            float x21 = e2[c] / d2;
            float x11 = e1[c] / d1;
            float gr = s.gnws[c] * rsg;
            s.Aarr[c]  = x21 * gr;
            s.Kpart[c] = x21 * (s.gnbs[c] - gr * m) + x11 * s.b3s[c];
        }
    }
    __syncthreads();

    // ---- F1: conv + gated-norm, 2 rows x 8 cols/thread, 4-way ci split ----
    {
        int cig = tid >> 7;              // ci group 0..3 -> ci {2cig, 2cig+1}
        int unit = tid & 127;
        int ip = unit >> 3;              // row pair 0..15
        int j0 = (unit & 7) << 3;        // cols j0..j0+7
        int i0 = ip << 1;                // output rows i0, i0+1
        float init = 0.f;
        if (cig == 0) {
            init = ((s.Kpart[0] + s.Kpart[1]) + (s.Kpart[2] + s.Kpart[3]))
                 + ((s.Kpart[4] + s.Kpart[5]) + (s.Kpart[6] + s.Kpart[7]));
        }
        float acc0[8], acc1[8];
        #pragma unroll
        for (int p = 0; p < 8; p++) { acc0[p] = init; acc1[p] = init; }

        #pragma unroll
        for (int cq = 0; cq < 2; cq++) {
            int ci = (cig << 1) + cq;
            const float* wc = &s.Weff[ci * 9];
            float c0w = wc[0], c1w = wc[1], c2w = wc[2];
            float c3w = wc[3], c4w = wc[4], c5w = wc[5];
            float c6w = wc[6], c7w = wc[7], c8w = wc[8];
            float aci = s.Aarr[ci];
            float coef0 = aci * s.sh[ci][i0];
            float coef1 = aci * s.sh[ci][i0 + 1];
            float4 swa = *(const float4*)&s.sw[ci][j0];
            float4 swb = *(const float4*)&s.sw[ci][j0 + 4];
            float swp[8] = {swa.x, swa.y, swa.z, swa.w, swb.x, swb.y, swb.z, swb.w};
            float w[12];
            ld12(&s.tile[ci][i0][j0], w);
            #pragma unroll
            for (int p = 0; p < 8; p++)
                acc0[p] += c0w * w[p + 1] + c1w * w[p + 2] + c2w * w[p + 3];
            ld12(&s.tile[ci][i0 + 1][j0], w);
            #pragma unroll
            for (int p = 0; p < 8; p++) {
                acc0[p] += c3w * w[p + 1] + c4w * w[p + 2] + c5w * w[p + 3]
                         + coef0 * swp[p] * w[p + 2];
                acc1[p] += c0w * w[p + 1] + c1w * w[p + 2] + c2w * w[p + 3];
            }
            ld12(&s.tile[ci][i0 + 2][j0], w);
            #pragma unroll
            for (int p = 0; p < 8; p++) {
                acc0[p] += c6w * w[p + 1] + c7w * w[p + 2] + c8w * w[p + 3];
                acc1[p] += c3w * w[p + 1] + c4w * w[p + 2] + c5w * w[p + 3]
                         + coef1 * swp[p] * w[p + 2];
            }
            ld12(&s.tile[ci][i0 + 3][j0], w);
            #pragma unroll
            for (int p = 0; p < 8; p++)
                acc1[p] += c6w * w[p + 1] + c7w * w[p + 2] + c8w * w[p + 3];
        }
        *(float4*)&s.accp[cig][i0][j0]     = make_float4(acc0[0], acc0[1], acc0[2], acc0[3]);
        *(float4*)&s.accp[cig][i0][j0 + 4] = make_float4(acc0[4], acc0[5], acc0[6], acc0[7]);
        *(float4*)&s.accp[cig][i0 + 1][j0]     = make_float4(acc1[0], acc1[1], acc1[2], acc1[3]);
        *(float4*)&s.accp[cig][i0 + 1][j0 + 4] = make_float4(acc1[4], acc1[5], acc1[6], acc1[7]);
    }
    __syncthreads();

    // ---- F2: wt = sigmoid(sum of 4 partials); out = gx(fp16 tile) * wt ----
    // init is nonzero only for cig==0, so the 4-way sum carries it exactly once.
    {
        int i = (tid >> 4) & 31;
        int j4 = (tid & 15) << 2;
        float4 p0 = *(const float4*)&s.accp[0][i][j4];
        float4 p1 = *(const float4*)&s.accp[1][i][j4];
        float4 p2 = *(const float4*)&s.accp[2][i][j4];
        float4 p3 = *(const float4*)&s.accp[3][i][j4];
        float4 wv = make_float4(
            sigf((p0.x + p1.x) + (p2.x + p3.x)),
            sigf((p0.y + p1.y) + (p2.y + p3.y)),
            sigf((p0.z + p1.z) + (p2.z + p3.z)),
            sigf((p0.w + p1.w) + (p2.w + p3.w)));
        #pragma unroll
        for (int c = 0; c < 8; c++) {
            __half2 ha = *(const __half2*)&s.tile[c][i + 1][j4 + 2];
            __half2 hb = *(const __half2*)&s.tile[c][i + 1][j4 + 4];
            float2 fa = __half22float2(ha);
            float2 fb = __half22float2(hb);
            float4 o4 = make_float4(fa.x * wv.x, fa.y * wv.y, fb.x * wv.z, fb.y * wv.w);
            *reinterpret_cast<float4*>(&dst[c * 4096 + (rbase + i) * 64 + j4]) = o4;
        }
    }
}

extern "C" void kernel_launch(void* const* d_in, const int* in_sizes, int n_in,
                              void* d_out, int out_size) {
    (void)in_sizes; (void)n_in; (void)out_size;
    const float* x   = (const float*)d_in[0];
    const float* w1  = (const float*)d_in[1];
    const float* b1  = (const float*)d_in[2];
    const float* w3  = (const float*)d_in[3];
    const float* b3  = (const float*)d_in[4];
    const float* gnw = (const float*)d_in[5];
    const float* gnb = (const float*)d_in[6];
    float* out = (float*)d_out;

    size_t smem = sizeof(SmC);
    cudaFuncSetAttribute(fused_kernel, cudaFuncAttributeMaxDynamicSharedMemorySize, (int)smem);
    fused_kernel<<<2048, NTH, smem>>>(x, w1, b1, w3, b3, gnw, gnb, out);
}